// round 14
// baseline (speedup 1.0000x reference)
#include <cuda_runtime.h>
#include <cuda_bf16.h>
#include <math.h>
#include <stdint.h>

#define NN   50000
#define EE   500000
#define GG   64
#define DIN  128
#define ED   32
#define H1   256
#define H2   128
#define HD   64
#define OUTD 8
#define NCHUNK 49   // ceil(NN/1024)

// ---------------- scratch (device globals; no allocation allowed) ----------
__device__ float g_xl[(size_t)NN * H1];
__device__ float g_xr[(size_t)NN * H1];
__device__ float g_h1[(size_t)NN * H1];
__device__ float g_h2[(size_t)NN * H2];
__device__ float g_escore[EE];          // indexed by CSR position
__device__ float g_eself[NN];
__device__ float g_loopattr[(size_t)NN * ED];
__device__ int   g_deg[NN];
__device__ int   g_ptr[NN + 1];
__device__ int   g_cur[NN];
__device__ int   g_eid[EE];             // CSR pos -> original edge id
__device__ int   g_src_csr[EE];         // CSR pos -> src node
__device__ int   g_dst_csr[EE];         // CSR pos -> dst node
__device__ int   g_bsum[64];
__device__ float g_pool[GG * H2];

// ======================= helpers ==========================================
__device__ __forceinline__ uint32_t smem_u32(const void* p) {
    uint32_t a;
    asm("{ .reg .u64 t; cvta.to.shared.u64 t, %1; cvt.u32.u64 %0, t; }" : "=r"(a) : "l"(p));
    return a;
}
// pack two f32 (k-order: lo_k first) into bf16x2 word (low half = lo_k)
__device__ __forceinline__ uint32_t packbf(float lo_k, float hi_k) {
    uint32_t r;
    asm("cvt.rn.bf16x2.f32 %0, %1, %2;" : "=r"(r) : "f"(hi_k), "f"(lo_k));
    return r;
}
__device__ __forceinline__ void ldm_x4(uint32_t (&r)[4], uint32_t addr) {
    asm volatile("ldmatrix.sync.aligned.m8n8.x4.shared.b16 {%0,%1,%2,%3}, [%4];"
        : "=r"(r[0]), "=r"(r[1]), "=r"(r[2]), "=r"(r[3]) : "r"(addr));
}
__device__ __forceinline__ void ldm_x4t(uint32_t (&r)[4], uint32_t addr) {
    asm volatile("ldmatrix.sync.aligned.m8n8.x4.trans.shared.b16 {%0,%1,%2,%3}, [%4];"
        : "=r"(r[0]), "=r"(r[1]), "=r"(r[2]), "=r"(r[3]) : "r"(addr));
}
__device__ __forceinline__ void mma_bf16(float (&c)[4], const uint32_t (&a)[4],
                                         uint32_t b0, uint32_t b1) {
    asm volatile("mma.sync.aligned.m16n8k16.row.col.f32.bf16.bf16.f32 "
        "{%0,%1,%2,%3},{%4,%5,%6,%7},{%8,%9},{%0,%1,%2,%3};"
        : "+f"(c[0]), "+f"(c[1]), "+f"(c[2]), "+f"(c[3])
        : "r"(a[0]), "r"(a[1]), "r"(a[2]), "r"(a[3]), "r"(b0), "r"(b1));
}
// convert float4 -> hi/lo bf16x2 pair words
__device__ __forceinline__ void cvt4(const float4& v, uint32_t& h01, uint32_t& h23,
                                     uint32_t& l01, uint32_t& l23) {
    h01 = packbf(v.x, v.y);
    h23 = packbf(v.z, v.w);
    float r0 = v.x - __uint_as_float(h01 << 16);
    float r1 = v.y - __uint_as_float(h01 & 0xffff0000u);
    float r2 = v.z - __uint_as_float(h23 << 16);
    float r3 = v.w - __uint_as_float(h23 & 0xffff0000u);
    l01 = packbf(r0, r1);
    l23 = packbf(r2, r3);
}
#define CP16(s, g)   asm volatile("cp.async.cg.shared.global [%0], [%1], 16;" :: "r"(s), "l"(g))
#define CP_COMMIT()  asm volatile("cp.async.commit_group;" ::: "memory")
#define CP_WAIT0()   asm volatile("cp.async.wait_group 0;" ::: "memory")
#define CP_WAIT1()   asm volatile("cp.async.wait_group 1;" ::: "memory")

// ======================= setup kernels ====================================
__global__ void k_hist(const int* __restrict__ edst) {
    int e = blockIdx.x * blockDim.x + threadIdx.x;
    if (e < EE) atomicAdd(&g_deg[edst[e]], 1);
}

__global__ void k_scan_partial() {
    __shared__ int sh[32];
    int tid = threadIdx.x;
    int i = blockIdx.x * 1024 + tid;
    int v = (i < NN) ? g_deg[i] : 0;
#pragma unroll
    for (int o = 16; o; o >>= 1) v += __shfl_xor_sync(0xffffffffu, v, o);
    if ((tid & 31) == 0) sh[tid >> 5] = v;
    __syncthreads();
    if (tid < 32) {
        int t = sh[tid];
#pragma unroll
        for (int o = 16; o; o >>= 1) t += __shfl_xor_sync(0xffffffffu, t, o);
        if (tid == 0) g_bsum[blockIdx.x] = t;
    }
}

__global__ void k_scan_bsum() {
    __shared__ int sh[64];
    int tid = threadIdx.x;
    int v = (tid < NCHUNK) ? g_bsum[tid] : 0;
    sh[tid] = v;
    __syncthreads();
    for (int off = 1; off < 64; off <<= 1) {
        int t = (tid >= off) ? sh[tid - off] : 0;
        __syncthreads();
        sh[tid] += t;
        __syncthreads();
    }
    if (tid < NCHUNK) g_bsum[tid] = sh[tid] - v;   // exclusive
    if (tid == 0) g_ptr[NN] = EE;
}

__global__ void k_scan_final() {
    __shared__ int sh[32];
    int tid = threadIdx.x, lane = tid & 31, wid = tid >> 5;
    int i = blockIdx.x * 1024 + tid;
    int v = (i < NN) ? g_deg[i] : 0;
    int incl = v;
#pragma unroll
    for (int o = 1; o < 32; o <<= 1) {
        int t = __shfl_up_sync(0xffffffffu, incl, o);
        if (lane >= o) incl += t;
    }
    if (lane == 31) sh[wid] = incl;
    __syncthreads();
    if (wid == 0) {
        int t = sh[lane];
#pragma unroll
        for (int o = 1; o < 32; o <<= 1) {
            int u = __shfl_up_sync(0xffffffffu, t, o);
            if (lane >= o) t += u;
        }
        sh[lane] = t;
    }
    __syncthreads();
    int base = g_bsum[blockIdx.x] + (wid ? sh[wid - 1] : 0);
    if (i < NN) g_ptr[i] = base + incl - v;
}

__global__ void k_scatter(const int* __restrict__ esrc, const int* __restrict__ edst) {
    int e = blockIdx.x * blockDim.x + threadIdx.x;
    if (e >= EE) return;
    int d = edst[e];
    int pos = g_ptr[d] + atomicAdd(&g_cur[d], 1);
    g_eid[pos] = e;
    g_src_csr[pos] = esrc[e];
    g_dst_csr[pos] = d;
}

__global__ void k_loopmean(const float* __restrict__ eattr) {
    int gw = (blockIdx.x * blockDim.x + threadIdx.x) >> 5;
    int lane = threadIdx.x & 31;
    if (gw >= NN) return;
    int beg = g_ptr[gw], end = g_ptr[gw + 1];
    float acc = 0.f;
    for (int t = beg; t < end; t++)
        acc += eattr[(size_t)g_eid[t] * ED + lane];
    g_loopattr[(size_t)gw * ED + lane] = acc / fmaxf((float)(end - beg), 1.f);
}

// ======================= mma.sync bf16x3 node GEMM (dual weight-set) ======
// cp.async double-buffered: raw fp32 chunks prefetched while current chunk's
// MMA runs; conversion reads from smem. Dynamic smem layout (bytes):
//   rawA[2]: 0, 16384      (128 rows x 128B)
//   rawB[2]: 32768, 49152  (2z x 32 rows x 256B)
//   sAhi 65536 (10240) | sAlo 75776 (10240)
//   sBhi 86016 (9216)  | sBlo 95232 (9216)   -> total 104448
#define STRA 20   // A smem row stride in uint32 (40 bf16)
#define STRB 36   // B smem row stride in uint32 (72 bf16)
#define RAW_A_OFF 0
#define RAW_B_OFF 32768
#define CVA_HI 65536
#define CVA_LO 75776
#define CVB_HI 86016
#define CVB_LO 95232
#define MMA_SMEM 104448

template <int KTOT>
__global__ void __launch_bounds__(256, 2)
k_mma_nodeZ(const float* __restrict__ A,
            const float* __restrict__ W0, const float* __restrict__ bias0, float* __restrict__ out0,
            const float* __restrict__ W1, const float* __restrict__ bias1, float* __restrict__ out1,
            int M, int Nc) {
    extern __shared__ char smem[];
    uint32_t sb = smem_u32(smem);
    uint32_t* sAhi = (uint32_t*)(smem + CVA_HI);
    uint32_t* sAlo = (uint32_t*)(smem + CVA_LO);
    uint32_t* sBhi = (uint32_t*)(smem + CVB_HI);
    uint32_t* sBlo = (uint32_t*)(smem + CVB_LO);

    int tid = threadIdx.x, lane = tid & 31, w = tid >> 5;
    int wm = w & 3, wn = w >> 2;
    int row0 = blockIdx.x * 128, c0 = blockIdx.y * 64;
    constexpr int NK = KTOT / 32;

    float acc[2][2][4][4];   // [z][ii][j][q]
#pragma unroll
    for (int z = 0; z < 2; z++)
#pragma unroll
        for (int i = 0; i < 2; i++)
#pragma unroll
            for (int j = 0; j < 4; j++)
#pragma unroll
                for (int q = 0; q < 4; q++) acc[z][i][j][q] = 0.f;

    auto prefetch = [&](int stage, int k0) {
        // A: 1024 segs of 16B (128 rows x 8 segs)
#pragma unroll
        for (int t = 0; t < 4; t++) {
            int seg = tid + t * 256;
            int r = seg >> 3, c16 = seg & 7;
            uint32_t dst = sb + RAW_A_OFF + stage * 16384 + r * 128 + c16 * 16;
            if (row0 + r < M) {
                CP16(dst, A + (size_t)(row0 + r) * KTOT + k0 + c16 * 4);
            } else {
                *(float4*)(smem + RAW_A_OFF + stage * 16384 + r * 128 + c16 * 16) =
                    make_float4(0.f, 0.f, 0.f, 0.f);
            }
        }
        // B: 1024 segs (2z x 32 rows x 16 segs)
#pragma unroll
        for (int t = 0; t < 4; t++) {
            int seg = tid + t * 256;
            int z = seg >> 9, rem = seg & 511;
            int r = rem >> 4, c16 = rem & 15;
            const float* Wz = z ? W1 : W0;
            uint32_t dst = sb + RAW_B_OFF + stage * 16384 + z * 8192 + r * 256 + c16 * 16;
            CP16(dst, Wz + (size_t)(k0 + r) * Nc + c0 + c16 * 4);
        }
    };

    prefetch(0, 0);
    CP_COMMIT();

    for (int i = 0; i < NK; i++) {
        int cur = i & 1;
        if (i + 1 < NK) {
            prefetch(cur ^ 1, (i + 1) * 32);
            CP_COMMIT();
            CP_WAIT1();
        } else {
            CP_WAIT0();
        }
        __syncthreads();

        // ---- convert raw fp32 (smem) -> bf16 hi/lo buffers
        const char* rawA = smem + RAW_A_OFF + cur * 16384;
        const char* rawB = smem + RAW_B_OFF + cur * 16384;
#pragma unroll
        for (int t = 0; t < 4; t++) {
            int idx = tid + t * 256;
            int r = idx >> 3, c4 = (idx & 7) * 4;
            float4 v = *(const float4*)(rawA + r * 128 + c4 * 4);
            uint32_t h01, h23, l01, l23;
            cvt4(v, h01, h23, l01, l23);
            int o = r * STRA + (c4 >> 1);
            sAhi[o] = h01; sAhi[o + 1] = h23;
            sAlo[o] = l01; sAlo[o + 1] = l23;
        }
#pragma unroll
        for (int t = 0; t < 4; t++) {
            int idx = tid + t * 256;
            int z = idx >> 9, rem = idx & 511;
            int r = rem >> 4, c4 = (rem & 15) * 4;
            float4 v = *(const float4*)(rawB + z * 8192 + r * 256 + c4 * 4);
            uint32_t h01, h23, l01, l23;
            cvt4(v, h01, h23, l01, l23);
            int o = (z * 32 + r) * STRB + (c4 >> 1);
            sBhi[o] = h01; sBhi[o + 1] = h23;
            sBlo[o] = l01; sBlo[o + 1] = l23;
        }
        __syncthreads();

#pragma unroll
        for (int s = 0; s < 2; s++) {
            uint32_t aH[2][4], aL[2][4];
#pragma unroll
            for (int ii = 0; ii < 2; ii++) {
                int tile = lane >> 3, rr = lane & 7;
                int row = wm * 32 + ii * 16 + (tile & 1) * 8 + rr;
                int kk = s * 16 + (tile >> 1) * 8;
                uint32_t off = (uint32_t)(row * STRA) * 4u + (uint32_t)kk * 2u;
                ldm_x4(aH[ii], sb + CVA_HI + off);
                ldm_x4(aL[ii], sb + CVA_LO + off);
            }
            int q = lane >> 3, rr = lane & 7;
            int krow = s * 16 + (q & 1) * 8 + rr;
#pragma unroll
            for (int z = 0; z < 2; z++) {
                uint32_t zb = (uint32_t)(z * 32 * STRB * 4);
                uint32_t bH4[2][4], bL4[2][4];
#pragma unroll
                for (int j2 = 0; j2 < 2; j2++) {
                    int ncol = wn * 32 + (j2 * 2 + (q >> 1)) * 8;
                    uint32_t off = (uint32_t)(krow * STRB) * 4u + (uint32_t)ncol * 2u;
                    ldm_x4t(bH4[j2], sb + CVB_HI + zb + off);
                    ldm_x4t(bL4[j2], sb + CVB_LO + zb + off);
                }
#pragma unroll
                for (int ii = 0; ii < 2; ii++)
#pragma unroll
                    for (int j = 0; j < 4; j++) {
                        uint32_t bh0 = bH4[j >> 1][(j & 1) * 2];
                        uint32_t bh1 = bH4[j >> 1][(j & 1) * 2 + 1];
                        uint32_t bl0 = bL4[j >> 1][(j & 1) * 2];
                        uint32_t bl1 = bL4[j >> 1][(j & 1) * 2 + 1];
                        mma_bf16(acc[z][ii][j], aH[ii], bh0, bh1);
                        mma_bf16(acc[z][ii][j], aH[ii], bl0, bl1);
                        mma_bf16(acc[z][ii][j], aL[ii], bh0, bh1);
                    }
            }
        }
        __syncthreads();
    }

    int g = lane >> 2, tg = lane & 3;
#pragma unroll
    for (int z = 0; z < 2; z++) {
        const float* bias = z ? bias1 : bias0;
        float* out        = z ? out1 : out0;
#pragma unroll
        for (int i = 0; i < 2; i++) {
            int r1 = row0 + wm * 32 + i * 16 + g;
            int r2 = r1 + 8;
#pragma unroll
            for (int j = 0; j < 4; j++) {
                int col = c0 + wn * 32 + j * 8 + tg * 2;
                float2 bv = *(const float2*)&bias[col];
                if (r1 < M) {
                    float2 o = make_float2(acc[z][i][j][0] + bv.x, acc[z][i][j][1] + bv.y);
                    *(float2*)&out[(size_t)r1 * Nc + col] = o;
                }
                if (r2 < M) {
                    float2 o = make_float2(acc[z][i][j][2] + bv.x, acc[z][i][j][3] + bv.y);
                    *(float2*)&out[(size_t)r2 * Nc + col] = o;
                }
            }
        }
    }
}

// ======================= tensorized edge-score kernel (CSR order) =========
template <int C>
__global__ void __launch_bounds__(256, 2)
k_score_mma(const float* __restrict__ eattr, const float* __restrict__ We,
            const float* __restrict__ att,
            const float* __restrict__ xl, const float* __restrict__ xr) {
    constexpr int STRC = C / 2 + 4;            // We smem row stride (u32)
    constexpr int ASZ = 128 * STRA * 4;        // 10240
    constexpr int BSZ = 32 * STRC * 4;
    constexpr int OFF_ALO = ASZ;
    constexpr int OFF_BHI = 2 * ASZ;
    constexpr int OFF_BLO = 2 * ASZ + BSZ;
    constexpr int OFF_SRC = 2 * ASZ + 2 * BSZ;
    constexpr int OFF_DST = OFF_SRC + 512;
    constexpr int OFF_ATT = OFF_DST + 512;
    constexpr int OFF_SC  = OFF_ATT + C * 4;

    extern __shared__ char smem[];
    uint32_t sb = smem_u32(smem);
    uint32_t* sAhi = (uint32_t*)smem;
    uint32_t* sAlo = (uint32_t*)(smem + OFF_ALO);
    uint32_t* sBhi = (uint32_t*)(smem + OFF_BHI);
    uint32_t* sBlo = (uint32_t*)(smem + OFF_BLO);
    int* ssrc   = (int*)(smem + OFF_SRC);
    int* sdst   = (int*)(smem + OFF_DST);
    float* satt = (float*)(smem + OFF_ATT);
    float* sscore = (float*)(smem + OFF_SC);

    int tid = threadIdx.x, lane = tid & 31, w = tid >> 5;
    int wm = w & 3, wn = w >> 2;
    int r0 = blockIdx.x * 128;

    // ---- A: eattr rows (via CSR eid) 128x32 -> hi/lo bf16
#pragma unroll
    for (int t = 0; t < 4; t++) {
        int idx = tid + t * 256;
        int r = idx >> 3, c4 = (idx & 7) * 4;
        float4 v = make_float4(0.f, 0.f, 0.f, 0.f);
        if (r0 + r < EE) {
            int e = g_eid[r0 + r];
            v = *(const float4*)&eattr[(size_t)e * ED + c4];
        }
        uint32_t h01, h23, l01, l23;
        cvt4(v, h01, h23, l01, l23);
        int o = r * STRA + (c4 >> 1);
        sAhi[o] = h01; sAhi[o + 1] = h23;
        sAlo[o] = l01; sAlo[o + 1] = l23;
    }
    // ---- B: We 32xC -> hi/lo bf16
    for (int idx = tid; idx < 32 * (C / 4); idx += 256) {
        int r = idx / (C / 4), c4 = (idx % (C / 4)) * 4;
        float4 v = *(const float4*)&We[(size_t)r * C + c4];
        uint32_t h01, h23, l01, l23;
        cvt4(v, h01, h23, l01, l23);
        int o = r * STRC + (c4 >> 1);
        sBhi[o] = h01; sBhi[o + 1] = h23;
        sBlo[o] = l01; sBlo[o + 1] = l23;
    }
    if (tid < 128) {
        int t = r0 + tid;
        ssrc[tid] = (t < EE) ? g_src_csr[t] : 0;
        sdst[tid] = (t < EE) ? g_dst_csr[t] : 0;
        sscore[tid] = 0.f;
    }
    for (int c = tid; c < C; c += 256) satt[c] = att[c];
    __syncthreads();

    // ---- A fragments (K=32 fixed, loaded once)
    uint32_t aH[2][2][4], aL[2][2][4];   // [s][ii]
#pragma unroll
    for (int s = 0; s < 2; s++)
#pragma unroll
        for (int ii = 0; ii < 2; ii++) {
            int tile = lane >> 3, rr = lane & 7;
            int row = wm * 32 + ii * 16 + (tile & 1) * 8 + rr;
            int kk = s * 16 + (tile >> 1) * 8;
            uint32_t off = (uint32_t)(row * STRA) * 4u + (uint32_t)kk * 2u;
            ldm_x4(aH[s][ii], sb + off);
            ldm_x4(aL[s][ii], sb + OFF_ALO + off);
        }

    int g = lane >> 2, tg = lane & 3;
    float sc[2][2] = {{0.f, 0.f}, {0.f, 0.f}};   // [ii][rowhalf]

#pragma unroll
    for (int nb = 0; nb < C / 64; nb++) {
        float acc[2][4][4];
#pragma unroll
        for (int ii = 0; ii < 2; ii++)
#pragma unroll
            for (int j = 0; j < 4; j++)
#pragma unroll
                for (int q = 0; q < 4; q++) acc[ii][j][q] = 0.f;

#pragma unroll
        for (int s = 0; s < 2; s++) {
            int q = lane >> 3, rr = lane & 7;
            int krow = s * 16 + (q & 1) * 8 + rr;
            uint32_t bH4[2][4], bL4[2][4];
#pragma unroll
            for (int j2 = 0; j2 < 2; j2++) {
                int ncol = nb * 64 + wn * 32 + (j2 * 2 + (q >> 1)) * 8;
                uint32_t off = (uint32_t)(krow * STRC) * 4u + (uint32_t)ncol * 2u;
                ldm_x4t(bH4[j2], sb + OFF_BHI + off);
                ldm_x4t(bL4[j2], sb + OFF_BLO + off);
            }
#pragma unroll
            for (int ii = 0; ii < 2; ii++)
#pragma unroll
                for (int j = 0; j < 4; j++) {
                    uint32_t bh0 = bH4[j >> 1][(j & 1) * 2];
                    uint32_t bh1 = bH4[j >> 1][(j & 1) * 2 + 1];
                    uint32_t bl0 = bL4[j >> 1][(j & 1) * 2];
                    uint32_t bl1 = bL4[j >> 1][(j & 1) * 2 + 1];
                    mma_bf16(acc[ii][j], aH[s][ii], bh0, bh1);
                    mma_bf16(acc[ii][j], aH[s][ii], bl0, bl1);
                    mma_bf16(acc[ii][j], aL[s][ii], bh0, bh1);
                }
        }

        // ---- epilogue: gather xl/xr (xr has dst-run locality), leaky, att
#pragma unroll
        for (int ii = 0; ii < 2; ii++) {
            int row1 = wm * 32 + ii * 16 + g;
            int row2 = row1 + 8;
            int s1 = ssrc[row1], d1 = sdst[row1];
            int s2 = ssrc[row2], d2 = sdst[row2];
#pragma unroll
            for (int j = 0; j < 4; j++) {
                int col = nb * 64 + wn * 32 + j * 8 + tg * 2;
                float2 av = *(float2*)&satt[col];
                float2 l1 = *(const float2*)&xl[(size_t)s1 * C + col];
                float2 q1 = *(const float2*)&xr[(size_t)d1 * C + col];
                float2 l2 = *(const float2*)&xl[(size_t)s2 * C + col];
                float2 q2 = *(const float2*)&xr[(size_t)d2 * C + col];
                float t0 = acc[ii][j][0] + l1.x + q1.x; t0 = t0 > 0.f ? t0 : 0.2f * t0;
                float t1 = acc[ii][j][1] + l1.y + q1.y; t1 = t1 > 0.f ? t1 : 0.2f * t1;
                float t2 = acc[ii][j][2] + l2.x + q2.x; t2 = t2 > 0.f ? t2 : 0.2f * t2;
                float t3 = acc[ii][j][3] + l2.y + q2.y; t3 = t3 > 0.f ? t3 : 0.2f * t3;
                sc[ii][0] += av.x * t0 + av.y * t1;
                sc[ii][1] += av.x * t2 + av.y * t3;
            }
        }
    }

    // ---- reduce across tg lanes, combine across wn warps via smem atomics
#pragma unroll
    for (int ii = 0; ii < 2; ii++)
#pragma unroll
        for (int h = 0; h < 2; h++) {
            float v = sc[ii][h];
            v += __shfl_xor_sync(0xffffffffu, v, 1);
            v += __shfl_xor_sync(0xffffffffu, v, 2);
            if (tg == 0) {
                int row = wm * 32 + ii * 16 + g + h * 8;
                atomicAdd(&sscore[row], v);
            }
        }
    __syncthreads();
    if (tid < 128 && r0 + tid < EE) g_escore[r0 + tid] = sscore[tid];
}

// ======================= self-loop score per node =========================
template <int C>
__global__ void k_eself(const float* __restrict__ We, const float* __restrict__ att,
                        const float* __restrict__ xl, const float* __restrict__ xr) {
    int gw = (blockIdx.x * blockDim.x + threadIdx.x) >> 5;
    int lane = threadIdx.x & 31;
    if (gw >= NN) return;
    float la = g_loopattr[(size_t)gw * ED + lane];
    float acc = 0.f;
#pragma unroll
    for (int jj = 0; jj < C / 32; jj++) {
        int j = jj * 32 + lane;
        float v = xl[(size_t)gw * C + j] + xr[(size_t)gw * C + j];
#pragma unroll
        for (int k = 0; k < ED; k++)
            v += __shfl_sync(0xffffffffu, la, k) * We[k * C + j];
        v = v > 0.f ? v : 0.2f * v;
        acc += att[j] * v;
    }
#pragma unroll
    for (int off = 16; off; off >>= 1) acc += __shfl_xor_sync(0xffffffffu, acc, off);
    if (lane == 0) g_eself[gw] = acc;
}

// ======================= softmax + aggregation (warp/node, CSR) ===========
template <int C>
__global__ void k_aggregate(const float* __restrict__ bias,
                            const float* __restrict__ xl,
                            float* __restrict__ outp) {
    int gw = (blockIdx.x * blockDim.x + threadIdx.x) >> 5;
    int lane = threadIdx.x & 31;
    if (gw >= NN) return;
    int beg = g_ptr[gw], end = g_ptr[gw + 1];

    float m = g_eself[gw];
    for (int t = beg + lane; t < end; t += 32) m = fmaxf(m, g_escore[t]);
#pragma unroll
    for (int off = 16; off; off >>= 1) m = fmaxf(m, __shfl_xor_sync(0xffffffffu, m, off));

    float4 acc[C / 128];
#pragma unroll
    for (int jj = 0; jj < C / 128; jj++) acc[jj] = make_float4(0.f, 0.f, 0.f, 0.f);
    float denom = 0.f;

    // unrolled-by-2 edge loop for MLP
    int t = beg;
    for (; t + 1 < end; t += 2) {
        float w0 = expf(g_escore[t] - m);
        float w1 = expf(g_escore[t + 1] - m);
        int s0 = g_src_csr[t], s1 = g_src_csr[t + 1];
        denom += w0 + w1;
#pragma unroll
        for (int jj = 0; jj < C / 128; jj++) {
            float4 x0 = *(const float4*)&xl[(size_t)s0 * C + jj * 128 + lane * 4];
            float4 x1 = *(const float4*)&xl[(size_t)s1 * C + jj * 128 + lane * 4];
            acc[jj].x += w0 * x0.x + w1 * x1.x;
            acc[jj].y += w0 * x0.y + w1 * x1.y;
            acc[jj].z += w0 * x0.z + w1 * x1.z;
            acc[jj].w += w0 * x0.w + w1 * x1.w;
        }
    }
    if (t < end) {
        float w0 = expf(g_escore[t] - m);
        int s0 = g_src_csr[t];
        denom += w0;
#pragma unroll
        for (int jj = 0; jj < C / 128; jj++) {
            float4 x0 = *(const float4*)&xl[(size_t)s0 * C + jj * 128 + lane * 4];
            acc[jj].x += w0 * x0.x; acc[jj].y += w0 * x0.y;
            acc[jj].z += w0 * x0.z; acc[jj].w += w0 * x0.w;
        }
    }
    float ws = expf(g_eself[gw] - m);
    denom += ws;
#pragma unroll
    for (int jj = 0; jj < C / 128; jj++) {
        float4 x4 = *(const float4*)&xl[(size_t)gw * C + jj * 128 + lane * 4];
        acc[jj].x += ws * x4.x; acc[jj].y += ws * x4.y;
        acc[jj].z += ws * x4.z; acc[jj].w += ws * x4.w;
    }

    float inv = 1.f / denom;
#pragma unroll
    for (int jj = 0; jj < C / 128; jj++) {
        int c = jj * 128 + lane * 4;
        float4 b4 = *(const float4*)&bias[c];
        float4 o;
        o.x = fmaxf(acc[jj].x * inv + b4.x, 0.f);
        o.y = fmaxf(acc[jj].y * inv + b4.y, 0.f);
        o.z = fmaxf(acc[jj].z * inv + b4.z, 0.f);
        o.w = fmaxf(acc[jj].w * inv + b4.w, 0.f);
        *(float4*)&outp[(size_t)gw * C + c] = o;
    }
}

// ======================= global mean pool =================================
#define NPB 196
__global__ void k_pool2(const int* __restrict__ batch) {
    int tid = threadIdx.x;                 // 128 threads = H2 columns
    int n0 = blockIdx.x * NPB;
    int n1 = min(n0 + NPB, NN);
    if (n0 >= n1) return;
    int curg = batch[n0];
    float acc = 0.f;
    for (int n = n0; n < n1; n++) {
        int g = batch[n];
        if (g != curg) {
            atomicAdd(&g_pool[curg * H2 + tid], acc);
            acc = 0.f;
            curg = g;
        }
        acc += g_h2[(size_t)n * H2 + tid];
    }
    atomicAdd(&g_pool[curg * H2 + tid], acc);
}

// ======================= MLP head =========================================
__device__ __forceinline__ int lowerb(const int* b, int val) {
    int lo = 0, hi = NN;
    while (lo < hi) { int m = (lo + hi) >> 1; if (b[m] < val) lo = m + 1; else hi = m; }
    return lo;
}

__global__ void k_head(const int* __restrict__ batch,
                       const float* __restrict__ Wd1, const float* __restrict__ bd1,
                       const float* __restrict__ gma, const float* __restrict__ bta,
                       const float* __restrict__ mean, const float* __restrict__ var,
                       const float* __restrict__ Wd2, const float* __restrict__ bd2,
                       float* __restrict__ out) {
    __shared__ float sp[GG * H2];
    __shared__ float sh[GG * HD];
    __shared__ float scnt[GG];
    int tid = threadIdx.x;
    if (tid < GG)
        scnt[tid] = (float)(lowerb(batch, tid + 1) - lowerb(batch, tid));
    __syncthreads();
    for (int idx = tid; idx < GG * H2; idx += blockDim.x) {
        int g = idx / H2;
        sp[idx] = g_pool[idx] / fmaxf(scnt[g], 1.f);
    }
    __syncthreads();
    for (int idx = tid; idx < GG * HD; idx += blockDim.x) {
        int g = idx / HD, h = idx - g * HD;
        float a = bd1[h];
        for (int k = 0; k < H2; k++) a += sp[g * H2 + k] * Wd1[k * HD + h];
        a = (a - mean[h]) / sqrtf(var[h] + 1e-5f) * gma[h] + bta[h];
        a = a > 0.f ? a : 0.1f * a;
        sh[idx] = a;
    }
    __syncthreads();
    for (int idx = tid; idx < GG * OUTD; idx += blockDim.x) {
        int g = idx / OUTD, o = idx - g * OUTD;
        float a = bd2[o];
        for (int k = 0; k < HD; k++) a += sh[g * HD + k] * Wd2[k * OUTD + o];
        out[idx] = a;
    }
}

// ======================= launcher =========================================
extern "C" void kernel_launch(void* const* d_in, const int* in_sizes, int n_in,
                              void* d_out, int out_size) {
    const float* node_attr = (const float*)d_in[0];
    const float* edge_attr = (const float*)d_in[1];
    const int*   esrc      = (const int*)d_in[2];
    const int*   edst      = (const int*)d_in[3];
    const int*   batch     = (const int*)d_in[4];
    const float *Wl1 = (const float*)d_in[5],  *bl1 = (const float*)d_in[6];
    const float *Wr1 = (const float*)d_in[7],  *br1 = (const float*)d_in[8];
    const float *We1 = (const float*)d_in[9],  *att1 = (const float*)d_in[10], *b1 = (const float*)d_in[11];
    const float *Wl2 = (const float*)d_in[12], *bl2 = (const float*)d_in[13];
    const float *Wr2 = (const float*)d_in[14], *br2 = (const float*)d_in[15];
    const float *We2 = (const float*)d_in[16], *att2 = (const float*)d_in[17], *b2 = (const float*)d_in[18];
    const float *Wd1 = (const float*)d_in[19], *bd1 = (const float*)d_in[20];
    const float *gma = (const float*)d_in[21], *bta = (const float*)d_in[22];
    const float *mean = (const float*)d_in[23], *var = (const float*)d_in[24];
    const float *Wd2 = (const float*)d_in[25], *bd2 = (const float*)d_in[26];
    float* out = (float*)d_out;

    float *p_xl, *p_xr, *p_h1, *p_h2, *p_pool;
    int *p_deg, *p_cur;
    cudaGetSymbolAddress((void**)&p_xl, g_xl);
    cudaGetSymbolAddress((void**)&p_xr, g_xr);
    cudaGetSymbolAddress((void**)&p_h1, g_h1);
    cudaGetSymbolAddress((void**)&p_h2, g_h2);
    cudaGetSymbolAddress((void**)&p_pool, g_pool);
    cudaGetSymbolAddress((void**)&p_deg, g_deg);
    cudaGetSymbolAddress((void**)&p_cur, g_cur);

    // dynamic smem sizes
    const int SC1 = 2 * 10240 + 2 * (32 * (H1 / 2 + 4) * 4) + 512 + 512 + H1 * 4 + 512;
    const int SC2 = 2 * 10240 + 2 * (32 * (H2 / 2 + 4) * 4) + 512 + 512 + H2 * 4 + 512;
    cudaFuncSetAttribute(k_score_mma<H1>, cudaFuncAttributeMaxDynamicSharedMemorySize, SC1);
    cudaFuncSetAttribute(k_score_mma<H2>, cudaFuncAttributeMaxDynamicSharedMemorySize, SC2);
    cudaFuncSetAttribute(k_mma_nodeZ<DIN>, cudaFuncAttributeMaxDynamicSharedMemorySize, MMA_SMEM);
    cudaFuncSetAttribute(k_mma_nodeZ<H1>, cudaFuncAttributeMaxDynamicSharedMemorySize, MMA_SMEM);

    // fork-join resources (created once; creation is not a captured op)
    cudaStream_t sB;
    cudaEvent_t evIn, evCsr, evGemm1, evSelf1, evGemm2, evSelf2;
    cudaStreamCreateWithFlags(&sB, cudaStreamNonBlocking);
    cudaEventCreateWithFlags(&evIn, cudaEventDisableTiming);
    cudaEventCreateWithFlags(&evCsr, cudaEventDisableTiming);
    cudaEventCreateWithFlags(&evGemm1, cudaEventDisableTiming);
    cudaEventCreateWithFlags(&evSelf1, cudaEventDisableTiming);
    cudaEventCreateWithFlags(&evGemm2, cudaEventDisableTiming);
    cudaEventCreateWithFlags(&evSelf2, cudaEventDisableTiming);

    cudaMemsetAsync(p_deg, 0, NN * sizeof(int), 0);
    cudaMemsetAsync(p_cur, 0, NN * sizeof(int), 0);
    cudaMemsetAsync(p_pool, 0, GG * H2 * sizeof(float), 0);

    int nodeWB = (NN * 32 + 255) / 256;   // warp-per-node blocks
    int rowT = (NN + 127) / 128;          // 391
    int edgeT = (EE + 127) / 128;         // 3907

    // ---- fork: branch B = CSR construction; branch A (stream 0) = GEMM
    cudaEventRecord(evIn, 0);
    cudaStreamWaitEvent(sB, evIn, 0);
    k_hist<<<(EE + 255) / 256, 256, 0, sB>>>(edst);
    k_scan_partial<<<NCHUNK, 1024, 0, sB>>>();
    k_scan_bsum<<<1, 64, 0, sB>>>();
    k_scan_final<<<NCHUNK, 1024, 0, sB>>>();
    k_scatter<<<(EE + 255) / 256, 256, 0, sB>>>(esrc, edst);
    k_loopmean<<<nodeWB, 256, 0, sB>>>(edge_attr);
    cudaEventRecord(evCsr, sB);

    k_mma_nodeZ<DIN><<<dim3(rowT, H1 / 64), 256, MMA_SMEM, 0>>>(
        node_attr, Wl1, bl1, p_xl, Wr1, br1, p_xr, NN, H1);
    cudaEventRecord(evGemm1, 0);

    // ---- layer 1: score on stream 0 (needs CSR + xl/xr); eself on sB
    cudaStreamWaitEvent(0, evCsr, 0);
    k_score_mma<H1><<<edgeT, 256, SC1, 0>>>(edge_attr, We1, att1, p_xl, p_xr);
    cudaStreamWaitEvent(sB, evGemm1, 0);
    k_eself<H1><<<nodeWB, 256, 0, sB>>>(We1, att1, p_xl, p_xr);
    cudaEventRecord(evSelf1, sB);
    cudaStreamWaitEvent(0, evSelf1, 0);
    k_aggregate<H1><<<nodeWB, 256, 0, 0>>>(b1, p_xl, p_h1);

    // ---- layer 2
    k_mma_nodeZ<H1><<<dim3(rowT, H2 / 64), 256, MMA_SMEM, 0>>>(
        p_h1, Wl2, bl2, p_xl, Wr2, br2, p_xr, NN, H2);
    cudaEventRecord(evGemm2, 0);
    k_score_mma<H2><<<edgeT, 256, SC2, 0>>>(edge_attr, We2, att2, p_xl, p_xr);
    cudaStreamWaitEvent(sB, evGemm2, 0);
    k_eself<H2><<<nodeWB, 256, 0, sB>>>(We2, att2, p_xl, p_xr);
    cudaEventRecord(evSelf2, sB);
    cudaStreamWaitEvent(0, evSelf2, 0);
    k_aggregate<H2><<<nodeWB, 256, 0, 0>>>(b2, p_xl, p_h2);

    // ---- pool + head
    k_pool2<<<(NN + NPB - 1) / NPB, 128, 0, 0>>>(batch);
    k_head<<<1, 512, 0, 0>>>(batch, Wd1, bd1, gma, bta, mean, var, Wd2, bd2, out);
}

// round 15
// speedup vs baseline: 1.0249x; 1.0249x over previous
#include <cuda_runtime.h>
#include <cuda_bf16.h>
#include <math.h>
#include <stdint.h>

#define NN   50000
#define EE   500000
#define GG   64
#define DIN  128
#define ED   32
#define H1   256
#define H2   128
#define HD   64
#define OUTD 8
#define NCHUNK 49   // ceil(NN/1024)

// ---------------- scratch (device globals; no allocation allowed) ----------
__device__ float g_xl[(size_t)NN * H1];
__device__ float g_xr[(size_t)NN * H1];
__device__ float g_h1[(size_t)NN * H1];
__device__ float g_h2[(size_t)NN * H2];
__device__ float g_escore[EE];          // indexed by CSR position
__device__ float g_eself[NN];
__device__ float g_loopattr[(size_t)NN * ED];
__device__ int   g_deg[NN];
__device__ int   g_ptr[NN + 1];
__device__ int   g_cur[NN];
__device__ int   g_eid[EE];             // CSR pos -> original edge id
__device__ int   g_src_csr[EE];         // CSR pos -> src node
__device__ int   g_dst_csr[EE];         // CSR pos -> dst node
__device__ int   g_bsum[64];
__device__ float g_pool[GG * H2];

// ======================= helpers ==========================================
__device__ __forceinline__ uint32_t smem_u32(const void* p) {
    uint32_t a;
    asm("{ .reg .u64 t; cvta.to.shared.u64 t, %1; cvt.u32.u64 %0, t; }" : "=r"(a) : "l"(p));
    return a;
}
// pack two f32 (k-order: lo_k first) into bf16x2 word (low half = lo_k)
__device__ __forceinline__ uint32_t packbf(float lo_k, float hi_k) {
    uint32_t r;
    asm("cvt.rn.bf16x2.f32 %0, %1, %2;" : "=r"(r) : "f"(hi_k), "f"(lo_k));
    return r;
}
__device__ __forceinline__ void ldm_x4(uint32_t (&r)[4], uint32_t addr) {
    asm volatile("ldmatrix.sync.aligned.m8n8.x4.shared.b16 {%0,%1,%2,%3}, [%4];"
        : "=r"(r[0]), "=r"(r[1]), "=r"(r[2]), "=r"(r[3]) : "r"(addr));
}
__device__ __forceinline__ void ldm_x4t(uint32_t (&r)[4], uint32_t addr) {
    asm volatile("ldmatrix.sync.aligned.m8n8.x4.trans.shared.b16 {%0,%1,%2,%3}, [%4];"
        : "=r"(r[0]), "=r"(r[1]), "=r"(r[2]), "=r"(r[3]) : "r"(addr));
}
__device__ __forceinline__ void mma_bf16(float (&c)[4], const uint32_t (&a)[4],
                                         uint32_t b0, uint32_t b1) {
    asm volatile("mma.sync.aligned.m16n8k16.row.col.f32.bf16.bf16.f32 "
        "{%0,%1,%2,%3},{%4,%5,%6,%7},{%8,%9},{%0,%1,%2,%3};"
        : "+f"(c[0]), "+f"(c[1]), "+f"(c[2]), "+f"(c[3])
        : "r"(a[0]), "r"(a[1]), "r"(a[2]), "r"(a[3]), "r"(b0), "r"(b1));
}
// convert float4 -> hi/lo bf16x2 pair words
__device__ __forceinline__ void cvt4(const float4& v, uint32_t& h01, uint32_t& h23,
                                     uint32_t& l01, uint32_t& l23) {
    h01 = packbf(v.x, v.y);
    h23 = packbf(v.z, v.w);
    float r0 = v.x - __uint_as_float(h01 << 16);
    float r1 = v.y - __uint_as_float(h01 & 0xffff0000u);
    float r2 = v.z - __uint_as_float(h23 << 16);
    float r3 = v.w - __uint_as_float(h23 & 0xffff0000u);
    l01 = packbf(r0, r1);
    l23 = packbf(r2, r3);
}

// ======================= setup kernels ====================================
__global__ void k_hist(const int* __restrict__ edst) {
    int e = blockIdx.x * blockDim.x + threadIdx.x;
    if (e < EE) atomicAdd(&g_deg[edst[e]], 1);
}

__global__ void k_scan_partial() {
    __shared__ int sh[32];
    int tid = threadIdx.x;
    int i = blockIdx.x * 1024 + tid;
    int v = (i < NN) ? g_deg[i] : 0;
#pragma unroll
    for (int o = 16; o; o >>= 1) v += __shfl_xor_sync(0xffffffffu, v, o);
    if ((tid & 31) == 0) sh[tid >> 5] = v;
    __syncthreads();
    if (tid < 32) {
        int t = sh[tid];
#pragma unroll
        for (int o = 16; o; o >>= 1) t += __shfl_xor_sync(0xffffffffu, t, o);
        if (tid == 0) g_bsum[blockIdx.x] = t;
    }
}

__global__ void k_scan_bsum() {
    __shared__ int sh[64];
    int tid = threadIdx.x;
    int v = (tid < NCHUNK) ? g_bsum[tid] : 0;
    sh[tid] = v;
    __syncthreads();
    for (int off = 1; off < 64; off <<= 1) {
        int t = (tid >= off) ? sh[tid - off] : 0;
        __syncthreads();
        sh[tid] += t;
        __syncthreads();
    }
    if (tid < NCHUNK) g_bsum[tid] = sh[tid] - v;   // exclusive
    if (tid == 0) g_ptr[NN] = EE;
}

__global__ void k_scan_final() {
    __shared__ int sh[32];
    int tid = threadIdx.x, lane = tid & 31, wid = tid >> 5;
    int i = blockIdx.x * 1024 + tid;
    int v = (i < NN) ? g_deg[i] : 0;
    int incl = v;
#pragma unroll
    for (int o = 1; o < 32; o <<= 1) {
        int t = __shfl_up_sync(0xffffffffu, incl, o);
        if (lane >= o) incl += t;
    }
    if (lane == 31) sh[wid] = incl;
    __syncthreads();
    if (wid == 0) {
        int t = sh[lane];
#pragma unroll
        for (int o = 1; o < 32; o <<= 1) {
            int u = __shfl_up_sync(0xffffffffu, t, o);
            if (lane >= o) t += u;
        }
        sh[lane] = t;
    }
    __syncthreads();
    int base = g_bsum[blockIdx.x] + (wid ? sh[wid - 1] : 0);
    if (i < NN) g_ptr[i] = base + incl - v;
}

__global__ void k_scatter(const int* __restrict__ esrc, const int* __restrict__ edst) {
    int e = blockIdx.x * blockDim.x + threadIdx.x;
    if (e >= EE) return;
    int d = edst[e];
    int pos = g_ptr[d] + atomicAdd(&g_cur[d], 1);
    g_eid[pos] = e;
    g_src_csr[pos] = esrc[e];
    g_dst_csr[pos] = d;
}

__global__ void k_loopmean(const float* __restrict__ eattr) {
    int gw = (blockIdx.x * blockDim.x + threadIdx.x) >> 5;
    int lane = threadIdx.x & 31;
    if (gw >= NN) return;
    int beg = g_ptr[gw], end = g_ptr[gw + 1];
    float acc = 0.f;
    for (int t = beg; t < end; t++)
        acc += eattr[(size_t)g_eid[t] * ED + lane];
    g_loopattr[(size_t)gw * ED + lane] = acc / fmaxf((float)(end - beg), 1.f);
}

// ======================= mma.sync bf16x3 node GEMM (dual weight-set) ======
#define STRA 20   // A smem row stride in uint32 (40 bf16)
#define STRB 36   // B smem row stride in uint32 (72 bf16)

template <int KTOT>
__global__ void __launch_bounds__(256, 2)
k_mma_nodeZ(const float* __restrict__ A,
            const float* __restrict__ W0, const float* __restrict__ bias0, float* __restrict__ out0,
            const float* __restrict__ W1, const float* __restrict__ bias1, float* __restrict__ out1,
            int M, int Nc) {
    __shared__ __align__(16) uint32_t sAhi[128 * STRA];
    __shared__ __align__(16) uint32_t sAlo[128 * STRA];
    __shared__ __align__(16) uint32_t sBhi[2][32 * STRB];
    __shared__ __align__(16) uint32_t sBlo[2][32 * STRB];

    int tid = threadIdx.x, lane = tid & 31, w = tid >> 5;
    int wm = w & 3, wn = w >> 2;
    int row0 = blockIdx.x * 128, c0 = blockIdx.y * 64;

    uint32_t aHiB = smem_u32(sAhi), aLoB = smem_u32(sAlo);
    uint32_t bHiB0 = smem_u32(sBhi[0]), bLoB0 = smem_u32(sBlo[0]);

    float acc[2][2][4][4];   // [z][ii][j][q]
#pragma unroll
    for (int z = 0; z < 2; z++)
#pragma unroll
        for (int i = 0; i < 2; i++)
#pragma unroll
            for (int j = 0; j < 4; j++)
#pragma unroll
                for (int q = 0; q < 4; q++) acc[z][i][j][q] = 0.f;

    for (int k0 = 0; k0 < KTOT; k0 += 32) {
#pragma unroll
        for (int t = 0; t < 4; t++) {
            int idx = tid + t * 256;
            int r = idx >> 3, c4 = (idx & 7) * 4;
            float4 v = make_float4(0.f, 0.f, 0.f, 0.f);
            if (row0 + r < M)
                v = *(const float4*)&A[(size_t)(row0 + r) * KTOT + k0 + c4];
            uint32_t h01, h23, l01, l23;
            cvt4(v, h01, h23, l01, l23);
            int o = r * STRA + (c4 >> 1);
            sAhi[o] = h01; sAhi[o + 1] = h23;
            sAlo[o] = l01; sAlo[o + 1] = l23;
        }
#pragma unroll
        for (int t = 0; t < 4; t++) {
            int idx = tid + t * 256;           // 0..1023
            int z = idx >> 9;                  // 512 per z
            int rem = idx & 511;
            int r = rem >> 4, c4 = (rem & 15) * 4;
            const float* Wz = z ? W1 : W0;
            float4 v = *(const float4*)&Wz[(size_t)(k0 + r) * Nc + c0 + c4];
            uint32_t h01, h23, l01, l23;
            cvt4(v, h01, h23, l01, l23);
            int o = r * STRB + (c4 >> 1);
            sBhi[z][o] = h01; sBhi[z][o + 1] = h23;
            sBlo[z][o] = l01; sBlo[z][o + 1] = l23;
        }
        __syncthreads();

#pragma unroll
        for (int s = 0; s < 2; s++) {
            uint32_t aH[2][4], aL[2][4];
#pragma unroll
            for (int ii = 0; ii < 2; ii++) {
                int tile = lane >> 3, rr = lane & 7;
                int row = wm * 32 + ii * 16 + (tile & 1) * 8 + rr;
                int kk = s * 16 + (tile >> 1) * 8;
                uint32_t off = (uint32_t)(row * STRA) * 4u + (uint32_t)kk * 2u;
                ldm_x4(aH[ii], aHiB + off);
                ldm_x4(aL[ii], aLoB + off);
            }
            int q = lane >> 3, rr = lane & 7;
            int krow = s * 16 + (q & 1) * 8 + rr;
#pragma unroll
            for (int z = 0; z < 2; z++) {
                uint32_t zb = (uint32_t)(z * 32 * STRB * 4);
                uint32_t bH4[2][4], bL4[2][4];
#pragma unroll
                for (int j2 = 0; j2 < 2; j2++) {
                    int ncol = wn * 32 + (j2 * 2 + (q >> 1)) * 8;
                    uint32_t off = (uint32_t)(krow * STRB) * 4u + (uint32_t)ncol * 2u;
                    ldm_x4t(bH4[j2], bHiB0 + zb + off);
                    ldm_x4t(bL4[j2], bLoB0 + zb + off);
                }
#pragma unroll
                for (int ii = 0; ii < 2; ii++)
#pragma unroll
                    for (int j = 0; j < 4; j++) {
                        uint32_t bh0 = bH4[j >> 1][(j & 1) * 2];
                        uint32_t bh1 = bH4[j >> 1][(j & 1) * 2 + 1];
                        uint32_t bl0 = bL4[j >> 1][(j & 1) * 2];
                        uint32_t bl1 = bL4[j >> 1][(j & 1) * 2 + 1];
                        mma_bf16(acc[z][ii][j], aH[ii], bh0, bh1);
                        mma_bf16(acc[z][ii][j], aH[ii], bl0, bl1);
                        mma_bf16(acc[z][ii][j], aL[ii], bh0, bh1);
                    }
            }
        }
        __syncthreads();
    }

    int g = lane >> 2, tg = lane & 3;
#pragma unroll
    for (int z = 0; z < 2; z++) {
        const float* bias = z ? bias1 : bias0;
        float* out        = z ? out1 : out0;
#pragma unroll
        for (int i = 0; i < 2; i++) {
            int r1 = row0 + wm * 32 + i * 16 + g;
            int r2 = r1 + 8;
#pragma unroll
            for (int j = 0; j < 4; j++) {
                int col = c0 + wn * 32 + j * 8 + tg * 2;
                float2 bv = *(const float2*)&bias[col];
                if (r1 < M) {
                    float2 o = make_float2(acc[z][i][j][0] + bv.x, acc[z][i][j][1] + bv.y);
                    *(float2*)&out[(size_t)r1 * Nc + col] = o;
                }
                if (r2 < M) {
                    float2 o = make_float2(acc[z][i][j][2] + bv.x, acc[z][i][j][3] + bv.y);
                    *(float2*)&out[(size_t)r2 * Nc + col] = o;
                }
            }
        }
    }
}

// ======================= tensorized edge-score kernel (CSR order) =========
template <int C>
__global__ void __launch_bounds__(256, 2)
k_score_mma(const float* __restrict__ eattr, const float* __restrict__ We,
            const float* __restrict__ att,
            const float* __restrict__ xl, const float* __restrict__ xr) {
    constexpr int STRC = C / 2 + 4;            // We smem row stride (u32)
    constexpr int ASZ = 128 * STRA * 4;        // 10240
    constexpr int BSZ = 32 * STRC * 4;
    constexpr int OFF_ALO = ASZ;
    constexpr int OFF_BHI = 2 * ASZ;
    constexpr int OFF_BLO = 2 * ASZ + BSZ;
    constexpr int OFF_SRC = 2 * ASZ + 2 * BSZ;
    constexpr int OFF_DST = OFF_SRC + 512;
    constexpr int OFF_ATT = OFF_DST + 512;
    constexpr int OFF_SC  = OFF_ATT + C * 4;

    extern __shared__ char smem[];
    uint32_t sb = smem_u32(smem);
    uint32_t* sAhi = (uint32_t*)smem;
    uint32_t* sAlo = (uint32_t*)(smem + OFF_ALO);
    uint32_t* sBhi = (uint32_t*)(smem + OFF_BHI);
    uint32_t* sBlo = (uint32_t*)(smem + OFF_BLO);
    int* ssrc   = (int*)(smem + OFF_SRC);
    int* sdst   = (int*)(smem + OFF_DST);
    float* satt = (float*)(smem + OFF_ATT);
    float* sscore = (float*)(smem + OFF_SC);

    int tid = threadIdx.x, lane = tid & 31, w = tid >> 5;
    int wm = w & 3, wn = w >> 2;
    int r0 = blockIdx.x * 128;

    // ---- A: eattr rows (via CSR eid) 128x32 -> hi/lo bf16
#pragma unroll
    for (int t = 0; t < 4; t++) {
        int idx = tid + t * 256;
        int r = idx >> 3, c4 = (idx & 7) * 4;
        float4 v = make_float4(0.f, 0.f, 0.f, 0.f);
        if (r0 + r < EE) {
            int e = g_eid[r0 + r];
            v = *(const float4*)&eattr[(size_t)e * ED + c4];
        }
        uint32_t h01, h23, l01, l23;
        cvt4(v, h01, h23, l01, l23);
        int o = r * STRA + (c4 >> 1);
        sAhi[o] = h01; sAhi[o + 1] = h23;
        sAlo[o] = l01; sAlo[o + 1] = l23;
    }
    // ---- B: We 32xC -> hi/lo bf16
    for (int idx = tid; idx < 32 * (C / 4); idx += 256) {
        int r = idx / (C / 4), c4 = (idx % (C / 4)) * 4;
        float4 v = *(const float4*)&We[(size_t)r * C + c4];
        uint32_t h01, h23, l01, l23;
        cvt4(v, h01, h23, l01, l23);
        int o = r * STRC + (c4 >> 1);
        sBhi[o] = h01; sBhi[o + 1] = h23;
        sBlo[o] = l01; sBlo[o + 1] = l23;
    }
    if (tid < 128) {
        int t = r0 + tid;
        ssrc[tid] = (t < EE) ? g_src_csr[t] : 0;
        sdst[tid] = (t < EE) ? g_dst_csr[t] : 0;
        sscore[tid] = 0.f;
    }
    for (int c = tid; c < C; c += 256) satt[c] = att[c];
    __syncthreads();

    // ---- A fragments (K=32 fixed, loaded once)
    uint32_t aH[2][2][4], aL[2][2][4];   // [s][ii]
#pragma unroll
    for (int s = 0; s < 2; s++)
#pragma unroll
        for (int ii = 0; ii < 2; ii++) {
            int tile = lane >> 3, rr = lane & 7;
            int row = wm * 32 + ii * 16 + (tile & 1) * 8 + rr;
            int kk = s * 16 + (tile >> 1) * 8;
            uint32_t off = (uint32_t)(row * STRA) * 4u + (uint32_t)kk * 2u;
            ldm_x4(aH[s][ii], sb + off);
            ldm_x4(aL[s][ii], sb + OFF_ALO + off);
        }

    int g = lane >> 2, tg = lane & 3;
    float sc[2][2] = {{0.f, 0.f}, {0.f, 0.f}};   // [ii][rowhalf]

#pragma unroll
    for (int nb = 0; nb < C / 64; nb++) {
        float acc[2][4][4];
#pragma unroll
        for (int ii = 0; ii < 2; ii++)
#pragma unroll
            for (int j = 0; j < 4; j++)
#pragma unroll
                for (int q = 0; q < 4; q++) acc[ii][j][q] = 0.f;

#pragma unroll
        for (int s = 0; s < 2; s++) {
            int q = lane >> 3, rr = lane & 7;
            int krow = s * 16 + (q & 1) * 8 + rr;
            uint32_t bH4[2][4], bL4[2][4];
#pragma unroll
            for (int j2 = 0; j2 < 2; j2++) {
                int ncol = nb * 64 + wn * 32 + (j2 * 2 + (q >> 1)) * 8;
                uint32_t off = (uint32_t)(krow * STRC) * 4u + (uint32_t)ncol * 2u;
                ldm_x4t(bH4[j2], sb + OFF_BHI + off);
                ldm_x4t(bL4[j2], sb + OFF_BLO + off);
            }
#pragma unroll
            for (int ii = 0; ii < 2; ii++)
#pragma unroll
                for (int j = 0; j < 4; j++) {
                    uint32_t bh0 = bH4[j >> 1][(j & 1) * 2];
                    uint32_t bh1 = bH4[j >> 1][(j & 1) * 2 + 1];
                    uint32_t bl0 = bL4[j >> 1][(j & 1) * 2];
                    uint32_t bl1 = bL4[j >> 1][(j & 1) * 2 + 1];
                    mma_bf16(acc[ii][j], aH[s][ii], bh0, bh1);
                    mma_bf16(acc[ii][j], aH[s][ii], bl0, bl1);
                    mma_bf16(acc[ii][j], aL[s][ii], bh0, bh1);
                }
        }

        // ---- epilogue: gather xl/xr (xr has dst-run locality), leaky, att
#pragma unroll
        for (int ii = 0; ii < 2; ii++) {
            int row1 = wm * 32 + ii * 16 + g;
            int row2 = row1 + 8;
            int s1 = ssrc[row1], d1 = sdst[row1];
            int s2 = ssrc[row2], d2 = sdst[row2];
#pragma unroll
            for (int j = 0; j < 4; j++) {
                int col = nb * 64 + wn * 32 + j * 8 + tg * 2;
                float2 av = *(float2*)&satt[col];
                float2 l1 = *(const float2*)&xl[(size_t)s1 * C + col];
                float2 q1 = *(const float2*)&xr[(size_t)d1 * C + col];
                float2 l2 = *(const float2*)&xl[(size_t)s2 * C + col];
                float2 q2 = *(const float2*)&xr[(size_t)d2 * C + col];
                float t0 = acc[ii][j][0] + l1.x + q1.x; t0 = t0 > 0.f ? t0 : 0.2f * t0;
                float t1 = acc[ii][j][1] + l1.y + q1.y; t1 = t1 > 0.f ? t1 : 0.2f * t1;
                float t2 = acc[ii][j][2] + l2.x + q2.x; t2 = t2 > 0.f ? t2 : 0.2f * t2;
                float t3 = acc[ii][j][3] + l2.y + q2.y; t3 = t3 > 0.f ? t3 : 0.2f * t3;
                sc[ii][0] += av.x * t0 + av.y * t1;
                sc[ii][1] += av.x * t2 + av.y * t3;
            }
        }
    }

    // ---- reduce across tg lanes, combine across wn warps via smem atomics
#pragma unroll
    for (int ii = 0; ii < 2; ii++)
#pragma unroll
        for (int h = 0; h < 2; h++) {
            float v = sc[ii][h];
            v += __shfl_xor_sync(0xffffffffu, v, 1);
            v += __shfl_xor_sync(0xffffffffu, v, 2);
            if (tg == 0) {
                int row = wm * 32 + ii * 16 + g + h * 8;
                atomicAdd(&sscore[row], v);
            }
        }
    __syncthreads();
    if (tid < 128 && r0 + tid < EE) g_escore[r0 + tid] = sscore[tid];
}

// ======================= self-loop score per node =========================
template <int C>
__global__ void k_eself(const float* __restrict__ We, const float* __restrict__ att,
                        const float* __restrict__ xl, const float* __restrict__ xr) {
    int gw = (blockIdx.x * blockDim.x + threadIdx.x) >> 5;
    int lane = threadIdx.x & 31;
    if (gw >= NN) return;
    float la = g_loopattr[(size_t)gw * ED + lane];
    float acc = 0.f;
#pragma unroll
    for (int jj = 0; jj < C / 32; jj++) {
        int j = jj * 32 + lane;
        float v = xl[(size_t)gw * C + j] + xr[(size_t)gw * C + j];
#pragma unroll
        for (int k = 0; k < ED; k++)
            v += __shfl_sync(0xffffffffu, la, k) * We[k * C + j];
        v = v > 0.f ? v : 0.2f * v;
        acc += att[j] * v;
    }
#pragma unroll
    for (int off = 16; off; off >>= 1) acc += __shfl_xor_sync(0xffffffffu, acc, off);
    if (lane == 0) g_eself[gw] = acc;
}

// ======================= softmax + aggregation (warp/node, CSR) ===========
template <int C>
__global__ void k_aggregate(const float* __restrict__ bias,
                            const float* __restrict__ xl,
                            float* __restrict__ outp) {
    int gw = (blockIdx.x * blockDim.x + threadIdx.x) >> 5;
    int lane = threadIdx.x & 31;
    if (gw >= NN) return;
    int beg = g_ptr[gw], end = g_ptr[gw + 1];

    float m = g_eself[gw];
    for (int t = beg + lane; t < end; t += 32) m = fmaxf(m, g_escore[t]);
#pragma unroll
    for (int off = 16; off; off >>= 1) m = fmaxf(m, __shfl_xor_sync(0xffffffffu, m, off));

    float4 acc[C / 128];
#pragma unroll
    for (int jj = 0; jj < C / 128; jj++) acc[jj] = make_float4(0.f, 0.f, 0.f, 0.f);
    float denom = 0.f;

    // unrolled-by-2 edge loop for MLP
    int t = beg;
    for (; t + 1 < end; t += 2) {
        float w0 = expf(g_escore[t] - m);
        float w1 = expf(g_escore[t + 1] - m);
        int s0 = g_src_csr[t], s1 = g_src_csr[t + 1];
        denom += w0 + w1;
#pragma unroll
        for (int jj = 0; jj < C / 128; jj++) {
            float4 x0 = *(const float4*)&xl[(size_t)s0 * C + jj * 128 + lane * 4];
            float4 x1 = *(const float4*)&xl[(size_t)s1 * C + jj * 128 + lane * 4];
            acc[jj].x += w0 * x0.x + w1 * x1.x;
            acc[jj].y += w0 * x0.y + w1 * x1.y;
            acc[jj].z += w0 * x0.z + w1 * x1.z;
            acc[jj].w += w0 * x0.w + w1 * x1.w;
        }
    }
    if (t < end) {
        float w0 = expf(g_escore[t] - m);
        int s0 = g_src_csr[t];
        denom += w0;
#pragma unroll
        for (int jj = 0; jj < C / 128; jj++) {
            float4 x0 = *(const float4*)&xl[(size_t)s0 * C + jj * 128 + lane * 4];
            acc[jj].x += w0 * x0.x; acc[jj].y += w0 * x0.y;
            acc[jj].z += w0 * x0.z; acc[jj].w += w0 * x0.w;
        }
    }
    float ws = expf(g_eself[gw] - m);
    denom += ws;
#pragma unroll
    for (int jj = 0; jj < C / 128; jj++) {
        float4 x4 = *(const float4*)&xl[(size_t)gw * C + jj * 128 + lane * 4];
        acc[jj].x += ws * x4.x; acc[jj].y += ws * x4.y;
        acc[jj].z += ws * x4.z; acc[jj].w += ws * x4.w;
    }

    float inv = 1.f / denom;
#pragma unroll
    for (int jj = 0; jj < C / 128; jj++) {
        int c = jj * 128 + lane * 4;
        float4 b4 = *(const float4*)&bias[c];
        float4 o;
        o.x = fmaxf(acc[jj].x * inv + b4.x, 0.f);
        o.y = fmaxf(acc[jj].y * inv + b4.y, 0.f);
        o.z = fmaxf(acc[jj].z * inv + b4.z, 0.f);
        o.w = fmaxf(acc[jj].w * inv + b4.w, 0.f);
        *(float4*)&outp[(size_t)gw * C + c] = o;
    }
}

// ======================= global mean pool =================================
#define NPB 196
__global__ void k_pool2(const int* __restrict__ batch) {
    int tid = threadIdx.x;                 // 128 threads = H2 columns
    int n0 = blockIdx.x * NPB;
    int n1 = min(n0 + NPB, NN);
    if (n0 >= n1) return;
    int curg = batch[n0];
    float acc = 0.f;
    for (int n = n0; n < n1; n++) {
        int g = batch[n];
        if (g != curg) {
            atomicAdd(&g_pool[curg * H2 + tid], acc);
            acc = 0.f;
            curg = g;
        }
        acc += g_h2[(size_t)n * H2 + tid];
    }
    atomicAdd(&g_pool[curg * H2 + tid], acc);
}

// ======================= MLP head =========================================
__device__ __forceinline__ int lowerb(const int* b, int val) {
    int lo = 0, hi = NN;
    while (lo < hi) { int m = (lo + hi) >> 1; if (b[m] < val) lo = m + 1; else hi = m; }
    return lo;
}

__global__ void k_head(const int* __restrict__ batch,
                       const float* __restrict__ Wd1, const float* __restrict__ bd1,
                       const float* __restrict__ gma, const float* __restrict__ bta,
                       const float* __restrict__ mean, const float* __restrict__ var,
                       const float* __restrict__ Wd2, const float* __restrict__ bd2,
                       float* __restrict__ out) {
    __shared__ float sp[GG * H2];
    __shared__ float sh[GG * HD];
    __shared__ float scnt[GG];
    int tid = threadIdx.x;
    if (tid < GG)
        scnt[tid] = (float)(lowerb(batch, tid + 1) - lowerb(batch, tid));
    __syncthreads();
    for (int idx = tid; idx < GG * H2; idx += blockDim.x) {
        int g = idx / H2;
        sp[idx] = g_pool[idx] / fmaxf(scnt[g], 1.f);
    }
    __syncthreads();
    for (int idx = tid; idx < GG * HD; idx += blockDim.x) {
        int g = idx / HD, h = idx - g * HD;
        float a = bd1[h];
        for (int k = 0; k < H2; k++) a += sp[g * H2 + k] * Wd1[k * HD + h];
        a = (a - mean[h]) / sqrtf(var[h] + 1e-5f) * gma[h] + bta[h];
        a = a > 0.f ? a : 0.1f * a;
        sh[idx] = a;
    }
    __syncthreads();
    for (int idx = tid; idx < GG * OUTD; idx += blockDim.x) {
        int g = idx / OUTD, o = idx - g * OUTD;
        float a = bd2[o];
        for (int k = 0; k < HD; k++) a += sh[g * HD + k] * Wd2[k * OUTD + o];
        out[idx] = a;
    }
}

// ======================= launcher =========================================
extern "C" void kernel_launch(void* const* d_in, const int* in_sizes, int n_in,
                              void* d_out, int out_size) {
    const float* node_attr = (const float*)d_in[0];
    const float* edge_attr = (const float*)d_in[1];
    const int*   esrc      = (const int*)d_in[2];
    const int*   edst      = (const int*)d_in[3];
    const int*   batch     = (const int*)d_in[4];
    const float *Wl1 = (const float*)d_in[5],  *bl1 = (const float*)d_in[6];
    const float *Wr1 = (const float*)d_in[7],  *br1 = (const float*)d_in[8];
    const float *We1 = (const float*)d_in[9],  *att1 = (const float*)d_in[10], *b1 = (const float*)d_in[11];
    const float *Wl2 = (const float*)d_in[12], *bl2 = (const float*)d_in[13];
    const float *Wr2 = (const float*)d_in[14], *br2 = (const float*)d_in[15];
    const float *We2 = (const float*)d_in[16], *att2 = (const float*)d_in[17], *b2 = (const float*)d_in[18];
    const float *Wd1 = (const float*)d_in[19], *bd1 = (const float*)d_in[20];
    const float *gma = (const float*)d_in[21], *bta = (const float*)d_in[22];
    const float *mean = (const float*)d_in[23], *var = (const float*)d_in[24];
    const float *Wd2 = (const float*)d_in[25], *bd2 = (const float*)d_in[26];
    float* out = (float*)d_out;

    float *p_xl, *p_xr, *p_h1, *p_h2, *p_pool;
    int *p_deg, *p_cur;
    cudaGetSymbolAddress((void**)&p_xl, g_xl);
    cudaGetSymbolAddress((void**)&p_xr, g_xr);
    cudaGetSymbolAddress((void**)&p_h1, g_h1);
    cudaGetSymbolAddress((void**)&p_h2, g_h2);
    cudaGetSymbolAddress((void**)&p_pool, g_pool);
    cudaGetSymbolAddress((void**)&p_deg, g_deg);
    cudaGetSymbolAddress((void**)&p_cur, g_cur);

    // dynamic smem sizes for score kernels
    const int SC1 = 2 * 10240 + 2 * (32 * (H1 / 2 + 4) * 4) + 512 + 512 + H1 * 4 + 512;
    const int SC2 = 2 * 10240 + 2 * (32 * (H2 / 2 + 4) * 4) + 512 + 512 + H2 * 4 + 512;
    cudaFuncSetAttribute(k_score_mma<H1>, cudaFuncAttributeMaxDynamicSharedMemorySize, SC1);
    cudaFuncSetAttribute(k_score_mma<H2>, cudaFuncAttributeMaxDynamicSharedMemorySize, SC2);

    // fork-join resources (created once; creation is not a captured op)
    cudaStream_t sB;
    cudaEvent_t evIn, evCsr, evGemm1, evSelf1, evGemm2, evSelf2;
    cudaStreamCreateWithFlags(&sB, cudaStreamNonBlocking);
    cudaEventCreateWithFlags(&evIn, cudaEventDisableTiming);
    cudaEventCreateWithFlags(&evCsr, cudaEventDisableTiming);
    cudaEventCreateWithFlags(&evGemm1, cudaEventDisableTiming);
    cudaEventCreateWithFlags(&evSelf1, cudaEventDisableTiming);
    cudaEventCreateWithFlags(&evGemm2, cudaEventDisableTiming);
    cudaEventCreateWithFlags(&evSelf2, cudaEventDisableTiming);

    cudaMemsetAsync(p_deg, 0, NN * sizeof(int), 0);
    cudaMemsetAsync(p_cur, 0, NN * sizeof(int), 0);
    cudaMemsetAsync(p_pool, 0, GG * H2 * sizeof(float), 0);

    int nodeWB = (NN * 32 + 255) / 256;   // warp-per-node blocks
    int rowT = (NN + 127) / 128;          // 391
    int edgeT = (EE + 127) / 128;         // 3907

    // ---- fork: branch B = CSR construction; branch A (stream 0) = GEMM
    cudaEventRecord(evIn, 0);
    cudaStreamWaitEvent(sB, evIn, 0);
    k_hist<<<(EE + 255) / 256, 256, 0, sB>>>(edst);
    k_scan_partial<<<NCHUNK, 1024, 0, sB>>>();
    k_scan_bsum<<<1, 64, 0, sB>>>();
    k_scan_final<<<NCHUNK, 1024, 0, sB>>>();
    k_scatter<<<(EE + 255) / 256, 256, 0, sB>>>(esrc, edst);
    k_loopmean<<<nodeWB, 256, 0, sB>>>(edge_attr);
    cudaEventRecord(evCsr, sB);

    k_mma_nodeZ<DIN><<<dim3(rowT, H1 / 64), 256, 0, 0>>>(
        node_attr, Wl1, bl1, p_xl, Wr1, br1, p_xr, NN, H1);
    cudaEventRecord(evGemm1, 0);

    // ---- layer 1: score on stream 0 (needs CSR + xl/xr); eself on sB
    cudaStreamWaitEvent(0, evCsr, 0);
    k_score_mma<H1><<<edgeT, 256, SC1, 0>>>(edge_attr, We1, att1, p_xl, p_xr);
    cudaStreamWaitEvent(sB, evGemm1, 0);
    k_eself<H1><<<nodeWB, 256, 0, sB>>>(We1, att1, p_xl, p_xr);
    cudaEventRecord(evSelf1, sB);
    cudaStreamWaitEvent(0, evSelf1, 0);
    k_aggregate<H1><<<nodeWB, 256, 0, 0>>>(b1, p_xl, p_h1);

    // ---- layer 2
    k_mma_nodeZ<H1><<<dim3(rowT, H2 / 64), 256, 0, 0>>>(
        p_h1, Wl2, bl2, p_xl, Wr2, br2, p_xr, NN, H2);
    cudaEventRecord(evGemm2, 0);
    k_score_mma<H2><<<edgeT, 256, SC2, 0>>>(edge_attr, We2, att2, p_xl, p_xr);
    cudaStreamWaitEvent(sB, evGemm2, 0);
    k_eself<H2><<<nodeWB, 256, 0, sB>>>(We2, att2, p_xl, p_xr);
    cudaEventRecord(evSelf2, sB);
    cudaStreamWaitEvent(0, evSelf2, 0);
    k_aggregate<H2><<<nodeWB, 256, 0, 0>>>(b2, p_xl, p_h2);

    // ---- pool + head
    k_pool2<<<(NN + NPB - 1) / NPB, 128, 0, 0>>>(batch);
    k_head<<<1, 512, 0, 0>>>(batch, Wd1, bd1, gma, bta, mean, var, Wd2, bd2, out);
}

// round 16
// speedup vs baseline: 1.0318x; 1.0068x over previous
#include <cuda_runtime.h>
#include <cuda_bf16.h>
#include <math.h>
#include <stdint.h>

#define NN   50000
#define EE   500000
#define GG   64
#define DIN  128
#define ED   32
#define H1   256
#define H2   128
#define HD   64
#define OUTD 8
#define NCHUNK 49   // ceil(NN/1024)

// ---------------- scratch (device globals; no allocation allowed) ----------
__device__ float g_xl[(size_t)NN * H1];
__device__ float g_xr[(size_t)NN * H1];
__device__ float g_h1[(size_t)NN * H1];
__device__ float g_h2[(size_t)NN * H2];
__device__ float g_escore[EE];          // indexed by CSR position
__device__ float g_eself[NN];
__device__ float g_loopattr[(size_t)NN * ED];
__device__ int   g_deg[NN];
__device__ int   g_ptr[NN + 1];
__device__ int   g_cur[NN];
__device__ int   g_eid[EE];             // CSR pos -> original edge id
__device__ int   g_src_csr[EE];         // CSR pos -> src node
__device__ int   g_dst_csr[EE];         // CSR pos -> dst node
__device__ int   g_bsum[64];
__device__ float g_pool[GG * H2];
// pre-converted We (hi/lo bf16): layer1 at 0, layer2 at 32*H1
__device__ __nv_bfloat16 g_wehi[32 * H1 + 32 * H2];
__device__ __nv_bfloat16 g_welo[32 * H1 + 32 * H2];

// ======================= helpers ==========================================
__device__ __forceinline__ uint32_t smem_u32(const void* p) {
    uint32_t a;
    asm("{ .reg .u64 t; cvta.to.shared.u64 t, %1; cvt.u32.u64 %0, t; }" : "=r"(a) : "l"(p));
    return a;
}
// pack two f32 (k-order: lo_k first) into bf16x2 word (low half = lo_k)
__device__ __forceinline__ uint32_t packbf(float lo_k, float hi_k) {
    uint32_t r;
    asm("cvt.rn.bf16x2.f32 %0, %1, %2;" : "=r"(r) : "f"(hi_k), "f"(lo_k));
    return r;
}
__device__ __forceinline__ void ldm_x4(uint32_t (&r)[4], uint32_t addr) {
    asm volatile("ldmatrix.sync.aligned.m8n8.x4.shared.b16 {%0,%1,%2,%3}, [%4];"
        : "=r"(r[0]), "=r"(r[1]), "=r"(r[2]), "=r"(r[3]) : "r"(addr));
}
__device__ __forceinline__ void ldm_x4t(uint32_t (&r)[4], uint32_t addr) {
    asm volatile("ldmatrix.sync.aligned.m8n8.x4.trans.shared.b16 {%0,%1,%2,%3}, [%4];"
        : "=r"(r[0]), "=r"(r[1]), "=r"(r[2]), "=r"(r[3]) : "r"(addr));
}
__device__ __forceinline__ void mma_bf16(float (&c)[4], const uint32_t (&a)[4],
                                         uint32_t b0, uint32_t b1) {
    asm volatile("mma.sync.aligned.m16n8k16.row.col.f32.bf16.bf16.f32 "
        "{%0,%1,%2,%3},{%4,%5,%6,%7},{%8,%9},{%0,%1,%2,%3};"
        : "+f"(c[0]), "+f"(c[1]), "+f"(c[2]), "+f"(c[3])
        : "r"(a[0]), "r"(a[1]), "r"(a[2]), "r"(a[3]), "r"(b0), "r"(b1));
}
// convert float4 -> hi/lo bf16x2 pair words
__device__ __forceinline__ void cvt4(const float4& v, uint32_t& h01, uint32_t& h23,
                                     uint32_t& l01, uint32_t& l23) {
    h01 = packbf(v.x, v.y);
    h23 = packbf(v.z, v.w);
    float r0 = v.x - __uint_as_float(h01 << 16);
    float r1 = v.y - __uint_as_float(h01 & 0xffff0000u);
    float r2 = v.z - __uint_as_float(h23 << 16);
    float r3 = v.w - __uint_as_float(h23 & 0xffff0000u);
    l01 = packbf(r0, r1);
    l23 = packbf(r2, r3);
}

// ======================= setup kernels ====================================
__global__ void k_hist(const int* __restrict__ edst) {
    int e = blockIdx.x * blockDim.x + threadIdx.x;
    if (e < EE) atomicAdd(&g_deg[edst[e]], 1);
}

__global__ void k_scan_partial() {
    __shared__ int sh[32];
    int tid = threadIdx.x;
    int i = blockIdx.x * 1024 + tid;
    int v = (i < NN) ? g_deg[i] : 0;
#pragma unroll
    for (int o = 16; o; o >>= 1) v += __shfl_xor_sync(0xffffffffu, v, o);
    if ((tid & 31) == 0) sh[tid >> 5] = v;
    __syncthreads();
    if (tid < 32) {
        int t = sh[tid];
#pragma unroll
        for (int o = 16; o; o >>= 1) t += __shfl_xor_sync(0xffffffffu, t, o);
        if (tid == 0) g_bsum[blockIdx.x] = t;
    }
}

__global__ void k_scan_bsum() {
    __shared__ int sh[64];
    int tid = threadIdx.x;
    int v = (tid < NCHUNK) ? g_bsum[tid] : 0;
    sh[tid] = v;
    __syncthreads();
    for (int off = 1; off < 64; off <<= 1) {
        int t = (tid >= off) ? sh[tid - off] : 0;
        __syncthreads();
        sh[tid] += t;
        __syncthreads();
    }
    if (tid < NCHUNK) g_bsum[tid] = sh[tid] - v;   // exclusive
    if (tid == 0) g_ptr[NN] = EE;
}

__global__ void k_scan_final() {
    __shared__ int sh[32];
    int tid = threadIdx.x, lane = tid & 31, wid = tid >> 5;
    int i = blockIdx.x * 1024 + tid;
    int v = (i < NN) ? g_deg[i] : 0;
    int incl = v;
#pragma unroll
    for (int o = 1; o < 32; o <<= 1) {
        int t = __shfl_up_sync(0xffffffffu, incl, o);
        if (lane >= o) incl += t;
    }
    if (lane == 31) sh[wid] = incl;
    __syncthreads();
    if (wid == 0) {
        int t = sh[lane];
#pragma unroll
        for (int o = 1; o < 32; o <<= 1) {
            int u = __shfl_up_sync(0xffffffffu, t, o);
            if (lane >= o) t += u;
        }
        sh[lane] = t;
    }
    __syncthreads();
    int base = g_bsum[blockIdx.x] + (wid ? sh[wid - 1] : 0);
    if (i < NN) g_ptr[i] = base + incl - v;
}

__global__ void k_scatter(const int* __restrict__ esrc, const int* __restrict__ edst) {
    int e = blockIdx.x * blockDim.x + threadIdx.x;
    if (e >= EE) return;
    int d = edst[e];
    int pos = g_ptr[d] + atomicAdd(&g_cur[d], 1);
    g_eid[pos] = e;
    g_src_csr[pos] = esrc[e];
    g_dst_csr[pos] = d;
}

__global__ void k_loopmean(const float* __restrict__ eattr) {
    int gw = (blockIdx.x * blockDim.x + threadIdx.x) >> 5;
    int lane = threadIdx.x & 31;
    if (gw >= NN) return;
    int beg = g_ptr[gw], end = g_ptr[gw + 1];
    float acc = 0.f;
    for (int t = beg; t < end; t++)
        acc += eattr[(size_t)g_eid[t] * ED + lane];
    g_loopattr[(size_t)gw * ED + lane] = acc / fmaxf((float)(end - beg), 1.f);
}

// ======================= We pre-conversion (fp32 -> bf16 hi/lo) ===========
__global__ void k_convw(const float* __restrict__ W, __nv_bfloat16* __restrict__ hi,
                        __nv_bfloat16* __restrict__ lo, int n4) {
    int i = blockIdx.x * blockDim.x + threadIdx.x;
    if (i >= n4) return;
    float4 v = ((const float4*)W)[i];
    uint32_t h01, h23, l01, l23;
    cvt4(v, h01, h23, l01, l23);
    ((uint2*)hi)[i] = make_uint2(h01, h23);
    ((uint2*)lo)[i] = make_uint2(l01, l23);
}

// ======================= mma.sync bf16x3 node GEMM (dual weight-set) ======
#define STRA 20   // A smem row stride in uint32 (40 bf16)
#define STRB 36   // B smem row stride in uint32 (72 bf16)

template <int KTOT>
__global__ void __launch_bounds__(256, 2)
k_mma_nodeZ(const float* __restrict__ A,
            const float* __restrict__ W0, const float* __restrict__ bias0, float* __restrict__ out0,
            const float* __restrict__ W1, const float* __restrict__ bias1, float* __restrict__ out1,
            int M, int Nc) {
    __shared__ __align__(16) uint32_t sAhi[128 * STRA];
    __shared__ __align__(16) uint32_t sAlo[128 * STRA];
    __shared__ __align__(16) uint32_t sBhi[2][32 * STRB];
    __shared__ __align__(16) uint32_t sBlo[2][32 * STRB];

    int tid = threadIdx.x, lane = tid & 31, w = tid >> 5;
    int wm = w & 3, wn = w >> 2;
    int row0 = blockIdx.x * 128, c0 = blockIdx.y * 64;

    uint32_t aHiB = smem_u32(sAhi), aLoB = smem_u32(sAlo);
    uint32_t bHiB0 = smem_u32(sBhi[0]), bLoB0 = smem_u32(sBlo[0]);

    float acc[2][2][4][4];   // [z][ii][j][q]
#pragma unroll
    for (int z = 0; z < 2; z++)
#pragma unroll
        for (int i = 0; i < 2; i++)
#pragma unroll
            for (int j = 0; j < 4; j++)
#pragma unroll
                for (int q = 0; q < 4; q++) acc[z][i][j][q] = 0.f;

    for (int k0 = 0; k0 < KTOT; k0 += 32) {
#pragma unroll
        for (int t = 0; t < 4; t++) {
            int idx = tid + t * 256;
            int r = idx >> 3, c4 = (idx & 7) * 4;
            float4 v = make_float4(0.f, 0.f, 0.f, 0.f);
            if (row0 + r < M)
                v = *(const float4*)&A[(size_t)(row0 + r) * KTOT + k0 + c4];
            uint32_t h01, h23, l01, l23;
            cvt4(v, h01, h23, l01, l23);
            int o = r * STRA + (c4 >> 1);
            sAhi[o] = h01; sAhi[o + 1] = h23;
            sAlo[o] = l01; sAlo[o + 1] = l23;
        }
#pragma unroll
        for (int t = 0; t < 4; t++) {
            int idx = tid + t * 256;           // 0..1023
            int z = idx >> 9;                  // 512 per z
            int rem = idx & 511;
            int r = rem >> 4, c4 = (rem & 15) * 4;
            const float* Wz = z ? W1 : W0;
            float4 v = *(const float4*)&Wz[(size_t)(k0 + r) * Nc + c0 + c4];
            uint32_t h01, h23, l01, l23;
            cvt4(v, h01, h23, l01, l23);
            int o = r * STRB + (c4 >> 1);
            sBhi[z][o] = h01; sBhi[z][o + 1] = h23;
            sBlo[z][o] = l01; sBlo[z][o + 1] = l23;
        }
        __syncthreads();

#pragma unroll
        for (int s = 0; s < 2; s++) {
            uint32_t aH[2][4], aL[2][4];
#pragma unroll
            for (int ii = 0; ii < 2; ii++) {
                int tile = lane >> 3, rr = lane & 7;
                int row = wm * 32 + ii * 16 + (tile & 1) * 8 + rr;
                int kk = s * 16 + (tile >> 1) * 8;
                uint32_t off = (uint32_t)(row * STRA) * 4u + (uint32_t)kk * 2u;
                ldm_x4(aH[ii], aHiB + off);
                ldm_x4(aL[ii], aLoB + off);
            }
            int q = lane >> 3, rr = lane & 7;
            int krow = s * 16 + (q & 1) * 8 + rr;
#pragma unroll
            for (int z = 0; z < 2; z++) {
                uint32_t zb = (uint32_t)(z * 32 * STRB * 4);
                uint32_t bH4[2][4], bL4[2][4];
#pragma unroll
                for (int j2 = 0; j2 < 2; j2++) {
                    int ncol = wn * 32 + (j2 * 2 + (q >> 1)) * 8;
                    uint32_t off = (uint32_t)(krow * STRB) * 4u + (uint32_t)ncol * 2u;
                    ldm_x4t(bH4[j2], bHiB0 + zb + off);
                    ldm_x4t(bL4[j2], bLoB0 + zb + off);
                }
#pragma unroll
                for (int ii = 0; ii < 2; ii++)
#pragma unroll
                    for (int j = 0; j < 4; j++) {
                        uint32_t bh0 = bH4[j >> 1][(j & 1) * 2];
                        uint32_t bh1 = bH4[j >> 1][(j & 1) * 2 + 1];
                        uint32_t bl0 = bL4[j >> 1][(j & 1) * 2];
                        uint32_t bl1 = bL4[j >> 1][(j & 1) * 2 + 1];
                        mma_bf16(acc[z][ii][j], aH[ii], bh0, bh1);
                        mma_bf16(acc[z][ii][j], aH[ii], bl0, bl1);
                        mma_bf16(acc[z][ii][j], aL[ii], bh0, bh1);
                    }
            }
        }
        __syncthreads();
    }

    int g = lane >> 2, tg = lane & 3;
#pragma unroll
    for (int z = 0; z < 2; z++) {
        const float* bias = z ? bias1 : bias0;
        float* out        = z ? out1 : out0;
#pragma unroll
        for (int i = 0; i < 2; i++) {
            int r1 = row0 + wm * 32 + i * 16 + g;
            int r2 = r1 + 8;
#pragma unroll
            for (int j = 0; j < 4; j++) {
                int col = c0 + wn * 32 + j * 8 + tg * 2;
                float2 bv = *(const float2*)&bias[col];
                if (r1 < M) {
                    float2 o = make_float2(acc[z][i][j][0] + bv.x, acc[z][i][j][1] + bv.y);
                    *(float2*)&out[(size_t)r1 * Nc + col] = o;
                }
                if (r2 < M) {
                    float2 o = make_float2(acc[z][i][j][2] + bv.x, acc[z][i][j][3] + bv.y);
                    *(float2*)&out[(size_t)r2 * Nc + col] = o;
                }
            }
        }
    }
}

// ======================= tensorized edge-score kernel (CSR order) =========
// B (We) arrives pre-converted to bf16 hi/lo — no per-CTA conversion.
template <int C>
__global__ void __launch_bounds__(256, 2)
k_score_mma(const float* __restrict__ eattr,
            const __nv_bfloat16* __restrict__ Wehi, const __nv_bfloat16* __restrict__ Welo,
            const float* __restrict__ att,
            const float* __restrict__ xl, const float* __restrict__ xr) {
    constexpr int STRC = C / 2 + 4;            // We smem row stride (u32)
    constexpr int ASZ = 128 * STRA * 4;        // 10240
    constexpr int BSZ = 32 * STRC * 4;
    constexpr int OFF_ALO = ASZ;
    constexpr int OFF_BHI = 2 * ASZ;
    constexpr int OFF_BLO = 2 * ASZ + BSZ;
    constexpr int OFF_SRC = 2 * ASZ + 2 * BSZ;
    constexpr int OFF_DST = OFF_SRC + 512;
    constexpr int OFF_ATT = OFF_DST + 512;
    constexpr int OFF_SC  = OFF_ATT + C * 4;

    extern __shared__ char smem[];
    uint32_t sb = smem_u32(smem);
    uint32_t* sAhi = (uint32_t*)smem;
    uint32_t* sAlo = (uint32_t*)(smem + OFF_ALO);
    uint32_t* sBhi = (uint32_t*)(smem + OFF_BHI);
    uint32_t* sBlo = (uint32_t*)(smem + OFF_BLO);
    int* ssrc   = (int*)(smem + OFF_SRC);
    int* sdst   = (int*)(smem + OFF_DST);
    float* satt = (float*)(smem + OFF_ATT);
    float* sscore = (float*)(smem + OFF_SC);

    int tid = threadIdx.x, lane = tid & 31, w = tid >> 5;
    int wm = w & 3, wn = w >> 2;
    int r0 = blockIdx.x * 128;

    // ---- A: eattr rows (via CSR eid) 128x32 -> hi/lo bf16
#pragma unroll
    for (int t = 0; t < 4; t++) {
        int idx = tid + t * 256;
        int r = idx >> 3, c4 = (idx & 7) * 4;
        float4 v = make_float4(0.f, 0.f, 0.f, 0.f);
        if (r0 + r < EE) {
            int e = g_eid[r0 + r];
            v = *(const float4*)&eattr[(size_t)e * ED + c4];
        }
        uint32_t h01, h23, l01, l23;
        cvt4(v, h01, h23, l01, l23);
        int o = r * STRA + (c4 >> 1);
        sAhi[o] = h01; sAhi[o + 1] = h23;
        sAlo[o] = l01; sAlo[o + 1] = l23;
    }
    // ---- B: pre-converted We hi/lo, straight copy into smem layout
    for (int idx = tid; idx < 32 * (C / 4); idx += 256) {
        int r = idx / (C / 4), c4 = (idx % (C / 4)) * 4;
        uint2 hv = *(const uint2*)&Wehi[(size_t)r * C + c4];
        uint2 lv = *(const uint2*)&Welo[(size_t)r * C + c4];
        int o = r * STRC + (c4 >> 1);
        sBhi[o] = hv.x; sBhi[o + 1] = hv.y;
        sBlo[o] = lv.x; sBlo[o + 1] = lv.y;
    }
    if (tid < 128) {
        int t = r0 + tid;
        ssrc[tid] = (t < EE) ? g_src_csr[t] : 0;
        sdst[tid] = (t < EE) ? g_dst_csr[t] : 0;
        sscore[tid] = 0.f;
    }
    for (int c = tid; c < C; c += 256) satt[c] = att[c];
    __syncthreads();

    // ---- A fragments (K=32 fixed, loaded once)
    uint32_t aH[2][2][4], aL[2][2][4];   // [s][ii]
#pragma unroll
    for (int s = 0; s < 2; s++)
#pragma unroll
        for (int ii = 0; ii < 2; ii++) {
            int tile = lane >> 3, rr = lane & 7;
            int row = wm * 32 + ii * 16 + (tile & 1) * 8 + rr;
            int kk = s * 16 + (tile >> 1) * 8;
            uint32_t off = (uint32_t)(row * STRA) * 4u + (uint32_t)kk * 2u;
            ldm_x4(aH[s][ii], sb + off);
            ldm_x4(aL[s][ii], sb + OFF_ALO + off);
        }

    int g = lane >> 2, tg = lane & 3;
    float sc[2][2] = {{0.f, 0.f}, {0.f, 0.f}};   // [ii][rowhalf]

#pragma unroll
    for (int nb = 0; nb < C / 64; nb++) {
        float acc[2][4][4];
#pragma unroll
        for (int ii = 0; ii < 2; ii++)
#pragma unroll
            for (int j = 0; j < 4; j++)
#pragma unroll
                for (int q = 0; q < 4; q++) acc[ii][j][q] = 0.f;

#pragma unroll
        for (int s = 0; s < 2; s++) {
            int q = lane >> 3, rr = lane & 7;
            int krow = s * 16 + (q & 1) * 8 + rr;
            uint32_t bH4[2][4], bL4[2][4];
#pragma unroll
            for (int j2 = 0; j2 < 2; j2++) {
                int ncol = nb * 64 + wn * 32 + (j2 * 2 + (q >> 1)) * 8;
                uint32_t off = (uint32_t)(krow * STRC) * 4u + (uint32_t)ncol * 2u;
                ldm_x4t(bH4[j2], sb + OFF_BHI + off);
                ldm_x4t(bL4[j2], sb + OFF_BLO + off);
            }
#pragma unroll
            for (int ii = 0; ii < 2; ii++)
#pragma unroll
                for (int j = 0; j < 4; j++) {
                    uint32_t bh0 = bH4[j >> 1][(j & 1) * 2];
                    uint32_t bh1 = bH4[j >> 1][(j & 1) * 2 + 1];
                    uint32_t bl0 = bL4[j >> 1][(j & 1) * 2];
                    uint32_t bl1 = bL4[j >> 1][(j & 1) * 2 + 1];
                    mma_bf16(acc[ii][j], aH[s][ii], bh0, bh1);
                    mma_bf16(acc[ii][j], aH[s][ii], bl0, bl1);
                    mma_bf16(acc[ii][j], aL[s][ii], bh0, bh1);
                }
        }

        // ---- epilogue: gather xl/xr (xr has dst-run locality), leaky, att
#pragma unroll
        for (int ii = 0; ii < 2; ii++) {
            int row1 = wm * 32 + ii * 16 + g;
            int row2 = row1 + 8;
            int s1 = ssrc[row1], d1 = sdst[row1];
            int s2 = ssrc[row2], d2 = sdst[row2];
#pragma unroll
            for (int j = 0; j < 4; j++) {
                int col = nb * 64 + wn * 32 + j * 8 + tg * 2;
                float2 av = *(float2*)&satt[col];
                float2 l1 = *(const float2*)&xl[(size_t)s1 * C + col];
                float2 q1 = *(const float2*)&xr[(size_t)d1 * C + col];
                float2 l2 = *(const float2*)&xl[(size_t)s2 * C + col];
                float2 q2 = *(const float2*)&xr[(size_t)d2 * C + col];
                float t0 = acc[ii][j][0] + l1.x + q1.x; t0 = t0 > 0.f ? t0 : 0.2f * t0;
                float t1 = acc[ii][j][1] + l1.y + q1.y; t1 = t1 > 0.f ? t1 : 0.2f * t1;
                float t2 = acc[ii][j][2] + l2.x + q2.x; t2 = t2 > 0.f ? t2 : 0.2f * t2;
                float t3 = acc[ii][j][3] + l2.y + q2.y; t3 = t3 > 0.f ? t3 : 0.2f * t3;
                sc[ii][0] += av.x * t0 + av.y * t1;
                sc[ii][1] += av.x * t2 + av.y * t3;
            }
        }
    }

    // ---- reduce across tg lanes, combine across wn warps via smem atomics
#pragma unroll
    for (int ii = 0; ii < 2; ii++)
#pragma unroll
        for (int h = 0; h < 2; h++) {
            float v = sc[ii][h];
            v += __shfl_xor_sync(0xffffffffu, v, 1);
            v += __shfl_xor_sync(0xffffffffu, v, 2);
            if (tg == 0) {
                int row = wm * 32 + ii * 16 + g + h * 8;
                atomicAdd(&sscore[row], v);
            }
        }
    __syncthreads();
    if (tid < 128 && r0 + tid < EE) g_escore[r0 + tid] = sscore[tid];
}

// ======================= self-loop score per node =========================
template <int C>
__global__ void k_eself(const float* __restrict__ We, const float* __restrict__ att,
                        const float* __restrict__ xl, const float* __restrict__ xr) {
    int gw = (blockIdx.x * blockDim.x + threadIdx.x) >> 5;
    int lane = threadIdx.x & 31;
    if (gw >= NN) return;
    float la = g_loopattr[(size_t)gw * ED + lane];
    float acc = 0.f;
#pragma unroll
    for (int jj = 0; jj < C / 32; jj++) {
        int j = jj * 32 + lane;
        float v = xl[(size_t)gw * C + j] + xr[(size_t)gw * C + j];
#pragma unroll
        for (int k = 0; k < ED; k++)
            v += __shfl_sync(0xffffffffu, la, k) * We[k * C + j];
        v = v > 0.f ? v : 0.2f * v;
        acc += att[j] * v;
    }
#pragma unroll
    for (int off = 16; off; off >>= 1) acc += __shfl_xor_sync(0xffffffffu, acc, off);
    if (lane == 0) g_eself[gw] = acc;
}

// ======================= softmax + aggregation (warp/node, CSR) ===========
template <int C>
__global__ void k_aggregate(const float* __restrict__ bias,
                            const float* __restrict__ xl,
                            float* __restrict__ outp) {
    int gw = (blockIdx.x * blockDim.x + threadIdx.x) >> 5;
    int lane = threadIdx.x & 31;
    if (gw >= NN) return;
    int beg = g_ptr[gw], end = g_ptr[gw + 1];

    float m = g_eself[gw];
    for (int t = beg + lane; t < end; t += 32) m = fmaxf(m, g_escore[t]);
#pragma unroll
    for (int off = 16; off; off >>= 1) m = fmaxf(m, __shfl_xor_sync(0xffffffffu, m, off));

    float4 acc[C / 128];
#pragma unroll
    for (int jj = 0; jj < C / 128; jj++) acc[jj] = make_float4(0.f, 0.f, 0.f, 0.f);
    float denom = 0.f;

    // unrolled-by-2 edge loop for MLP
    int t = beg;
    for (; t + 1 < end; t += 2) {
        float w0 = __expf(g_escore[t] - m);
        float w1 = __expf(g_escore[t + 1] - m);
        int s0 = g_src_csr[t], s1 = g_src_csr[t + 1];
        denom += w0 + w1;
#pragma unroll
        for (int jj = 0; jj < C / 128; jj++) {
            float4 x0 = *(const float4*)&xl[(size_t)s0 * C + jj * 128 + lane * 4];
            float4 x1 = *(const float4*)&xl[(size_t)s1 * C + jj * 128 + lane * 4];
            acc[jj].x += w0 * x0.x + w1 * x1.x;
            acc[jj].y += w0 * x0.y + w1 * x1.y;
            acc[jj].z += w0 * x0.z + w1 * x1.z;
            acc[jj].w += w0 * x0.w + w1 * x1.w;
        }
    }
    if (t < end) {
        float w0 = __expf(g_escore[t] - m);
        int s0 = g_src_csr[t];
        denom += w0;
#pragma unroll
        for (int jj = 0; jj < C / 128; jj++) {
            float4 x0 = *(const float4*)&xl[(size_t)s0 * C + jj * 128 + lane * 4];
            acc[jj].x += w0 * x0.x; acc[jj].y += w0 * x0.y;
            acc[jj].z += w0 * x0.z; acc[jj].w += w0 * x0.w;
        }
    }
    float ws = __expf(g_eself[gw] - m);
    denom += ws;
#pragma unroll
    for (int jj = 0; jj < C / 128; jj++) {
        float4 x4 = *(const float4*)&xl[(size_t)gw * C + jj * 128 + lane * 4];
        acc[jj].x += ws * x4.x; acc[jj].y += ws * x4.y;
        acc[jj].z += ws * x4.z; acc[jj].w += ws * x4.w;
    }

    float inv = 1.f / denom;
#pragma unroll
    for (int jj = 0; jj < C / 128; jj++) {
        int c = jj * 128 + lane * 4;
        float4 b4 = *(const float4*)&bias[c];
        float4 o;
        o.x = fmaxf(acc[jj].x * inv + b4.x, 0.f);
        o.y = fmaxf(acc[jj].y * inv + b4.y, 0.f);
        o.z = fmaxf(acc[jj].z * inv + b4.z, 0.f);
        o.w = fmaxf(acc[jj].w * inv + b4.w, 0.f);
        *(float4*)&outp[(size_t)gw * C + c] = o;
    }
}

// ======================= global mean pool =================================
#define NPB 196
__global__ void k_pool2(const int* __restrict__ batch) {
    int tid = threadIdx.x;                 // 128 threads = H2 columns
    int n0 = blockIdx.x * NPB;
    int n1 = min(n0 + NPB, NN);
    if (n0 >= n1) return;
    int curg = batch[n0];
    float acc = 0.f;
    for (int n = n0; n < n1; n++) {
        int g = batch[n];
        if (g != curg) {
            atomicAdd(&g_pool[curg * H2 + tid], acc);
            acc = 0.f;
            curg = g;
        }
        acc += g_h2[(size_t)n * H2 + tid];
    }
    atomicAdd(&g_pool[curg * H2 + tid], acc);
}

// ======================= MLP head =========================================
__device__ __forceinline__ int lowerb(const int* b, int val) {
    int lo = 0, hi = NN;
    while (lo < hi) { int m = (lo + hi) >> 1; if (b[m] < val) lo = m + 1; else hi = m; }
    return lo;
}

__global__ void k_head(const int* __restrict__ batch,
                       const float* __restrict__ Wd1, const float* __restrict__ bd1,
                       const float* __restrict__ gma, const float* __restrict__ bta,
                       const float* __restrict__ mean, const float* __restrict__ var,
                       const float* __restrict__ Wd2, const float* __restrict__ bd2,
                       float* __restrict__ out) {
    __shared__ float sp[GG * H2];
    __shared__ float sh[GG * HD];
    __shared__ float scnt[GG];
    int tid = threadIdx.x;
    if (tid < GG)
        scnt[tid] = (float)(lowerb(batch, tid + 1) - lowerb(batch, tid));
    __syncthreads();
    for (int idx = tid; idx < GG * H2; idx += blockDim.x) {
        int g = idx / H2;
        sp[idx] = g_pool[idx] / fmaxf(scnt[g], 1.f);
    }
    __syncthreads();
    for (int idx = tid; idx < GG * HD; idx += blockDim.x) {
        int g = idx / HD, h = idx - g * HD;
        float a = bd1[h];
        for (int k = 0; k < H2; k++) a += sp[g * H2 + k] * Wd1[k * HD + h];
        a = (a - mean[h]) / sqrtf(var[h] + 1e-5f) * gma[h] + bta[h];
        a = a > 0.f ? a : 0.1f * a;
        sh[idx] = a;
    }
    __syncthreads();
    for (int idx = tid; idx < GG * OUTD; idx += blockDim.x) {
        int g = idx / OUTD, o = idx - g * OUTD;
        float a = bd2[o];
        for (int k = 0; k < HD; k++) a += sh[g * HD + k] * Wd2[k * OUTD + o];
        out[idx] = a;
    }
}

// ======================= launcher =========================================
extern "C" void kernel_launch(void* const* d_in, const int* in_sizes, int n_in,
                              void* d_out, int out_size) {
    const float* node_attr = (const float*)d_in[0];
    const float* edge_attr = (const float*)d_in[1];
    const int*   esrc      = (const int*)d_in[2];
    const int*   edst      = (const int*)d_in[3];
    const int*   batch     = (const int*)d_in[4];
    const float *Wl1 = (const float*)d_in[5],  *bl1 = (const float*)d_in[6];
    const float *Wr1 = (const float*)d_in[7],  *br1 = (const float*)d_in[8];
    const float *We1 = (const float*)d_in[9],  *att1 = (const float*)d_in[10], *b1 = (const float*)d_in[11];
    const float *Wl2 = (const float*)d_in[12], *bl2 = (const float*)d_in[13];
    const float *Wr2 = (const float*)d_in[14], *br2 = (const float*)d_in[15];
    const float *We2 = (const float*)d_in[16], *att2 = (const float*)d_in[17], *b2 = (const float*)d_in[18];
    const float *Wd1 = (const float*)d_in[19], *bd1 = (const float*)d_in[20];
    const float *gma = (const float*)d_in[21], *bta = (const float*)d_in[22];
    const float *mean = (const float*)d_in[23], *var = (const float*)d_in[24];
    const float *Wd2 = (const float*)d_in[25], *bd2 = (const float*)d_in[26];
    float* out = (float*)d_out;

    float *p_xl, *p_xr, *p_h1, *p_h2, *p_pool;
    int *p_deg, *p_cur;
    __nv_bfloat16 *p_wehi, *p_welo;
    cudaGetSymbolAddress((void**)&p_xl, g_xl);
    cudaGetSymbolAddress((void**)&p_xr, g_xr);
    cudaGetSymbolAddress((void**)&p_h1, g_h1);
    cudaGetSymbolAddress((void**)&p_h2, g_h2);
    cudaGetSymbolAddress((void**)&p_pool, g_pool);
    cudaGetSymbolAddress((void**)&p_deg, g_deg);
    cudaGetSymbolAddress((void**)&p_cur, g_cur);
    cudaGetSymbolAddress((void**)&p_wehi, g_wehi);
    cudaGetSymbolAddress((void**)&p_welo, g_welo);

    // dynamic smem sizes for score kernels
    const int SC1 = 2 * 10240 + 2 * (32 * (H1 / 2 + 4) * 4) + 512 + 512 + H1 * 4 + 512;
    const int SC2 = 2 * 10240 + 2 * (32 * (H2 / 2 + 4) * 4) + 512 + 512 + H2 * 4 + 512;
    cudaFuncSetAttribute(k_score_mma<H1>, cudaFuncAttributeMaxDynamicSharedMemorySize, SC1);
    cudaFuncSetAttribute(k_score_mma<H2>, cudaFuncAttributeMaxDynamicSharedMemorySize, SC2);

    // fork-join resources (created once; creation is not a captured op)
    cudaStream_t sB;
    cudaEvent_t evIn, evCsr, evGemm1, evSelf1, evGemm2, evSelf2;
    cudaStreamCreateWithFlags(&sB, cudaStreamNonBlocking);
    cudaEventCreateWithFlags(&evIn, cudaEventDisableTiming);
    cudaEventCreateWithFlags(&evCsr, cudaEventDisableTiming);
    cudaEventCreateWithFlags(&evGemm1, cudaEventDisableTiming);
    cudaEventCreateWithFlags(&evSelf1, cudaEventDisableTiming);
    cudaEventCreateWithFlags(&evGemm2, cudaEventDisableTiming);
    cudaEventCreateWithFlags(&evSelf2, cudaEventDisableTiming);

    cudaMemsetAsync(p_deg, 0, NN * sizeof(int), 0);
    cudaMemsetAsync(p_cur, 0, NN * sizeof(int), 0);
    cudaMemsetAsync(p_pool, 0, GG * H2 * sizeof(float), 0);

    int nodeWB = (NN * 32 + 255) / 256;   // warp-per-node blocks
    int rowT = (NN + 127) / 128;          // 391
    int edgeT = (EE + 127) / 128;         // 3907

    // ---- fork: branch B = We conversion + CSR construction; A = GEMM
    cudaEventRecord(evIn, 0);
    cudaStreamWaitEvent(sB, evIn, 0);
    k_convw<<<(32 * H1 / 4 + 255) / 256, 256, 0, sB>>>(We1, p_wehi, p_welo, 32 * H1 / 4);
    k_convw<<<(32 * H2 / 4 + 255) / 256, 256, 0, sB>>>(We2, p_wehi + 32 * H1, p_welo + 32 * H1, 32 * H2 / 4);
    k_hist<<<(EE + 255) / 256, 256, 0, sB>>>(edst);
    k_scan_partial<<<NCHUNK, 1024, 0, sB>>>();
    k_scan_bsum<<<1, 64, 0, sB>>>();
    k_scan_final<<<NCHUNK, 1024, 0, sB>>>();
    k_scatter<<<(EE + 255) / 256, 256, 0, sB>>>(esrc, edst);
    k_loopmean<<<nodeWB, 256, 0, sB>>>(edge_attr);
    cudaEventRecord(evCsr, sB);

    k_mma_nodeZ<DIN><<<dim3(rowT, H1 / 64), 256, 0, 0>>>(
        node_attr, Wl1, bl1, p_xl, Wr1, br1, p_xr, NN, H1);
    cudaEventRecord(evGemm1, 0);

    // ---- layer 1: score on stream 0 (needs CSR + xl/xr); eself on sB
    cudaStreamWaitEvent(0, evCsr, 0);
    k_score_mma<H1><<<edgeT, 256, SC1, 0>>>(edge_attr, p_wehi, p_welo, att1, p_xl, p_xr);
    cudaStreamWaitEvent(sB, evGemm1, 0);
    k_eself<H1><<<nodeWB, 256, 0, sB>>>(We1, att1, p_xl, p_xr);
    cudaEventRecord(evSelf1, sB);
    cudaStreamWaitEvent(0, evSelf1, 0);
    k_aggregate<H1><<<nodeWB, 256, 0, 0>>>(b1, p_xl, p_h1);

    // ---- layer 2
    k_mma_nodeZ<H1><<<dim3(rowT, H2 / 64), 256, 0, 0>>>(
        p_h1, Wl2, bl2, p_xl, Wr2, br2, p_xr, NN, H2);
    cudaEventRecord(evGemm2, 0);
    k_score_mma<H2><<<edgeT, 256, SC2, 0>>>(edge_attr, p_wehi + 32 * H1, p_welo + 32 * H1, att2, p_xl, p_xr);
    cudaStreamWaitEvent(sB, evGemm2, 0);
    k_eself<H2><<<nodeWB, 256, 0, sB>>>(We2, att2, p_xl, p_xr);
    cudaEventRecord(evSelf2, sB);
    cudaStreamWaitEvent(0, evSelf2, 0);
    k_aggregate<H2><<<nodeWB, 256, 0, 0>>>(b2, p_xl, p_h2);

    // ---- pool + head
    k_pool2<<<(NN + NPB - 1) / NPB, 128, 0, 0>>>(batch);
    k_head<<<1, 512, 0, 0>>>(batch, Wd1, bd1, gma, bta, mean, var, Wd2, bd2, out);
}